// round 3
// baseline (speedup 1.0000x reference)
#include <cuda_runtime.h>
#include <math.h>

#define NSIDE 128
#define SLICES 1024
#define PLANE 16777216ull   // 1024 * 128 * 128

// Scratch: Y1/Y2 stored [slice][qs][n-natural] as float2, qs = storage-permuted q
__device__ float2 g_Y1[SLICES * NSIDE * NSIDE];
__device__ float2 g_Y2[SLICES * NSIDE * NSIDE];

// ---------------------------------------------------------------------------
// Register/shuffle 128-pt FFT: 128 = 32 lanes x 4 regs.
// Input layout (P4):  thread t holds x[4t + j], j = reg 0..3
// Output layout (SP): thread b, reg k1 holds X[bitrev5(b) + 32*k1]
// Inverse consumes SP, produces P4, UNSCALED (x128); scaling folded by caller.
// All twiddles via sincospif on exact dyadic arguments (max accuracy).
// ---------------------------------------------------------------------------
struct Tw {
    float w16r, w16i, w8r, w8i, w4r, w4i, w2r, w2i;
    float c1, s1, c2, s2, c3, s3;
};

__device__ __forceinline__ void stage_tw(int t, int h, float& cr, float& ci)
{
    if (t & h) {
        // angle = -pi * (t & (h-1)) / h  (exact dyadic argument)
        sincospif(-(float)(t & (h - 1)) / (float)h, &ci, &cr);
    } else { cr = 1.0f; ci = 0.0f; }
}

__device__ __forceinline__ void make_tw(Tw& T, int t)
{
    int br = __brev(t) >> 27;
    // theta = 2*pi*br/128 -> sincospif(br/64)
    sincospif((float)br * (1.0f / 64.0f), &T.s1, &T.c1);
    sincospif((float)br * (1.0f / 32.0f), &T.s2, &T.c2);
    sincospif((float)(3 * br) * (1.0f / 64.0f), &T.s3, &T.c3);
    stage_tw(t, 16, T.w16r, T.w16i);
    stage_tw(t, 8,  T.w8r,  T.w8i);
    stage_tw(t, 4,  T.w4r,  T.w4i);
    stage_tw(t, 2,  T.w2r,  T.w2i);
}

__device__ __forceinline__ void cmulm(float& ar, float& ai, float br, float bi)
{
    float r = ar * br - ai * bi;
    ai = ar * bi + ai * br;
    ar = r;
}

template <int H>
__device__ __forceinline__ void lane_stage_f(float vr[4], float vi[4],
                                             float twr, float twi, int t)
{
    float e = (t & H) ? -1.0f : 1.0f;
#pragma unroll
    for (int r = 0; r < 4; ++r) {
        float pr = __shfl_xor_sync(0xffffffffu, vr[r], H);
        float pi = __shfl_xor_sync(0xffffffffu, vi[r], H);
        float ur = fmaf(e, vr[r], pr);
        float ui = fmaf(e, vi[r], pi);
        vr[r] = ur * twr - ui * twi;
        vi[r] = fmaf(ur, twi, ui * twr);
    }
}

__device__ __forceinline__ void lane_stage_f1(float vr[4], float vi[4], int t)
{
    float e = (t & 1) ? -1.0f : 1.0f;
#pragma unroll
    for (int r = 0; r < 4; ++r) {
        float pr = __shfl_xor_sync(0xffffffffu, vr[r], 1);
        float pi = __shfl_xor_sync(0xffffffffu, vi[r], 1);
        vr[r] = fmaf(e, vr[r], pr);
        vi[r] = fmaf(e, vi[r], pi);
    }
}

template <int H>
__device__ __forceinline__ void lane_stage_i(float vr[4], float vi[4],
                                             float twr, float twi, int t)
{
    float e = (t & H) ? -1.0f : 1.0f;
#pragma unroll
    for (int r = 0; r < 4; ++r) {
        float ar = fmaf(vi[r], twi, vr[r] * twr);
        float ai = vi[r] * twr - vr[r] * twi;
        float pr = __shfl_xor_sync(0xffffffffu, ar, H);
        float pi = __shfl_xor_sync(0xffffffffu, ai, H);
        vr[r] = fmaf(e, ar, pr);
        vi[r] = fmaf(e, ai, pi);
    }
}

__device__ __forceinline__ void lane_stage_i1(float vr[4], float vi[4], int t)
{
    float e = (t & 1) ? -1.0f : 1.0f;
#pragma unroll
    for (int r = 0; r < 4; ++r) {
        float pr = __shfl_xor_sync(0xffffffffu, vr[r], 1);
        float pi = __shfl_xor_sync(0xffffffffu, vi[r], 1);
        vr[r] = fmaf(e, vr[r], pr);
        vi[r] = fmaf(e, vi[r], pi);
    }
}

__device__ __forceinline__ void fft_fwd(float vr[4], float vi[4], const Tw& T, int t)
{
    lane_stage_f<16>(vr, vi, T.w16r, T.w16i, t);
    lane_stage_f<8>(vr, vi, T.w8r, T.w8i, t);
    lane_stage_f<4>(vr, vi, T.w4r, T.w4i, t);
    lane_stage_f<2>(vr, vi, T.w2r, T.w2i, t);
    lane_stage_f1(vr, vi, t);
    cmulm(vr[1], vi[1], T.c1, -T.s1);
    cmulm(vr[2], vi[2], T.c2, -T.s2);
    cmulm(vr[3], vi[3], T.c3, -T.s3);
    float s02r = vr[0] + vr[2], s02i = vi[0] + vi[2];
    float d02r = vr[0] - vr[2], d02i = vi[0] - vi[2];
    float s13r = vr[1] + vr[3], s13i = vi[1] + vi[3];
    float d13r = vr[1] - vr[3], d13i = vi[1] - vi[3];
    vr[0] = s02r + s13r; vi[0] = s02i + s13i;
    vr[2] = s02r - s13r; vi[2] = s02i - s13i;
    vr[1] = d02r + d13i; vi[1] = d02i - d13r;
    vr[3] = d02r - d13i; vi[3] = d02i + d13r;
}

__device__ __forceinline__ void fft_inv(float vr[4], float vi[4], const Tw& T, int t)
{
    float s02r = vr[0] + vr[2], s02i = vi[0] + vi[2];
    float d02r = vr[0] - vr[2], d02i = vi[0] - vi[2];
    float s13r = vr[1] + vr[3], s13i = vi[1] + vi[3];
    float d13r = vr[1] - vr[3], d13i = vi[1] - vi[3];
    vr[0] = s02r + s13r; vi[0] = s02i + s13i;
    vr[2] = s02r - s13r; vi[2] = s02i - s13i;
    vr[1] = d02r - d13i; vi[1] = d02i + d13r;
    vr[3] = d02r + d13i; vi[3] = d02i - d13r;
    cmulm(vr[1], vi[1], T.c1, T.s1);
    cmulm(vr[2], vi[2], T.c2, T.s2);
    cmulm(vr[3], vi[3], T.c3, T.s3);
    lane_stage_i1(vr, vi, t);
    lane_stage_i<2>(vr, vi, T.w2r, T.w2i, t);
    lane_stage_i<4>(vr, vi, T.w4r, T.w4i, t);
    lane_stage_i<8>(vr, vi, T.w8r, T.w8i, t);
    lane_stage_i<16>(vr, vi, T.w16r, T.w16i, t);
}

// Fast atan2: minimax deg-11 odd poly, abs err ~1e-5 rad.
// Branch-cut SIGN behavior identical to atan2f (copysign from y).
__device__ __forceinline__ float fatan2f(float y, float x)
{
    float ax = fabsf(x), ay = fabsf(y);
    float mx = fmaxf(ax, ay), mn = fminf(ax, ay);
    float a = __fdividef(mn, mx);
    float s = a * a;
    float p = -0.0117212f;
    p = fmaf(p, s, 0.05265332f);
    p = fmaf(p, s, -0.11643287f);
    p = fmaf(p, s, 0.19354346f);
    p = fmaf(p, s, -0.33262347f);
    p = fmaf(p, s, 0.99997726f);
    float r = p * a;
    if (ay > ax) r = 1.57079632679f - r;
    if (x < 0.0f) r = 3.14159265359f - r;
    return copysignf(r, y);
}

// ---------------------------------------------------------------------------
// P1
// ---------------------------------------------------------------------------
__global__ void __launch_bounds__(512) p1_kernel(const float* __restrict__ x)
{
    extern __shared__ float sm[];
    float* Fre = sm;
    float* Fim = sm + 16384;

    const int s   = blockIdx.x;
    const int tid = threadIdx.x;
    const int u   = tid >> 5;
    const int t   = tid & 31;

    Tw T;
    make_tw(T, t);

    const float4* xs = (const float4*)(x + (size_t)s * (NSIDE * NSIDE));

#pragma unroll 1
    for (int it = 0; it < 8; ++it) {
        int m = it * 16 + u;
        float4 v = xs[m * 32 + t];
        float vr[4] = { v.x, v.y, v.z, v.w };
        float vi[4] = { 0.0f, 0.0f, 0.0f, 0.0f };
        fft_fwd(vr, vi, T, t);
        int C = (m >> 2) & 31;
        int rowb = m << 7;
#pragma unroll
        for (int k1 = 0; k1 < 4; ++k1) {
            int sc = (t + (k1 << 5)) ^ C;
            Fre[rowb + sc] = vr[k1];
            Fim[rowb + sc] = vi[k1];
        }
    }
    __syncthreads();

    const float scale = 1.0f / 16384.0f;
    const int brv = __brev(t) >> 27;

#pragma unroll 1
    for (int it = 0; it < 8; ++it) {
        int qs = it * 16 + u;
        int q_idx = (__brev(qs & 31) >> 27) + (qs & 96);
        float kq = (q_idx < 64) ? (float)q_idx : (float)(q_idx - 128);

        float vr[4], vi[4];
#pragma unroll
        for (int j = 0; j < 4; ++j) {
            int p = 4 * t + j;
            int sc = qs ^ t;
            vr[j] = Fre[(p << 7) + sc];
            vi[j] = Fim[(p << 7) + sc];
        }
        fft_fwd(vr, vi, T, t);

        float fr[4], fi[4];
#pragma unroll
        for (int k1 = 0; k1 < 4; ++k1) { fr[k1] = vr[k1]; fi[k1] = vi[k1]; }

        // G1 = (i*kp - kq) * F * scale
#pragma unroll
        for (int k1 = 0; k1 < 4; ++k1) {
            int p_idx = brv + (k1 << 5);
            float kp = (p_idx < 64) ? (float)p_idx : (float)(p_idx - 128);
            float w1r = -kq * scale, w1i = kp * scale;
            vr[k1] = fr[k1] * w1r - fi[k1] * w1i;
            vi[k1] = fr[k1] * w1i + fi[k1] * w1r;
        }
        fft_inv(vr, vi, T, t);
        {
            float4* y = (float4*)(g_Y1 + ((size_t)s * NSIDE + qs) * NSIDE + 4 * t);
            __stcs(y,     make_float4(vr[0], vi[0], vr[1], vi[1]));
            __stcs(y + 1, make_float4(vr[2], vi[2], vr[3], vi[3]));
        }

        // G2 = ((kq^2 - kp^2) - i*2*kp*kq) * F * scale
#pragma unroll
        for (int k1 = 0; k1 < 4; ++k1) {
            int p_idx = brv + (k1 << 5);
            float kp = (p_idx < 64) ? (float)p_idx : (float)(p_idx - 128);
            float w2r = (kq * kq - kp * kp) * scale;
            float w2i = -2.0f * kp * kq * scale;
            vr[k1] = fr[k1] * w2r - fi[k1] * w2i;
            vi[k1] = fr[k1] * w2i + fi[k1] * w2r;
        }
        fft_inv(vr, vi, T, t);
        {
            float4* y = (float4*)(g_Y2 + ((size_t)s * NSIDE + qs) * NSIDE + 4 * t);
            __stcs(y,     make_float4(vr[0], vi[0], vr[1], vi[1]));
            __stcs(y + 1, make_float4(vr[2], vi[2], vr[3], vi[3]));
        }
    }
}

// ---------------------------------------------------------------------------
// P2
// ---------------------------------------------------------------------------
__global__ void __launch_bounds__(512, 2) p2_kernel(float* __restrict__ out,
                                                    const float* __restrict__ df,
                                                    const float* __restrict__ d2f)
{
    extern __shared__ float sm[];
    float* T1r = sm;
    float* T1i = T1r + 4224;
    float* T2r = T1i + 4224;
    float* T2i = T2r + 4224;

    const int s    = blockIdx.x;
    const int m0   = blockIdx.y * 32;
    const int tid  = threadIdx.x;
    const int u    = tid >> 5;
    const int t    = tid & 31;

    Tw T;
    make_tw(T, t);

    // float4 = 2 adjacent pixels (float2 each)
    const float4* y1v = (const float4*)(g_Y1 + (size_t)s * (NSIDE * NSIDE));
    const float4* y2v = (const float4*)(g_Y2 + (size_t)s * (NSIDE * NSIDE));
    const int mb = blockIdx.y * 16;   // m0/2 in float4 units

#pragma unroll
    for (int i = 0; i < 4; ++i) {
        int e  = i * 512 + tid;
        int q  = e >> 4;          // 0..127
        int mp = e & 15;          // pair index 0..15
        float4 v1 = __ldcs(y1v + q * 64 + mb + mp);
        T1r[q * 33 + 2 * mp]     = v1.x;
        T1i[q * 33 + 2 * mp]     = v1.y;
        T1r[q * 33 + 2 * mp + 1] = v1.z;
        T1i[q * 33 + 2 * mp + 1] = v1.w;
        float4 v2 = __ldcs(y2v + q * 64 + mb + mp);
        T2r[q * 33 + 2 * mp]     = v2.x;
        T2i[q * 33 + 2 * mp]     = v2.y;
        T2r[q * 33 + 2 * mp + 1] = v2.z;
        T2i[q * 33 + 2 * mp + 1] = v2.w;
    }
    __syncthreads();

    const int c = s & 63;
    float df0 = df[2 * c], df1 = df[2 * c + 1];
    float ed  = expf(df0);
    float dfcr = ed * cosf(df1), dfci = ed * sinf(df1);
    float d20 = d2f[2 * c], d21 = d2f[2 * c + 1];
    float inv_nf = 0.5f / (dfcr * dfcr + dfci * dfci);
    float hrr = (d20 * dfcr + d21 * dfci) * inv_nf;
    float hri = (d21 * dfcr - d20 * dfci) * inv_nf;

    const float EPS2   = 1e-6f;
    const float LN_EPS = -6.9077552790f;
    const float TR_MIN = -2.5902671570f;

#pragma unroll 1
    for (int iter = 0; iter < 2; ++iter) {
        int mm = iter * 16 + u;
        int m  = m0 + mm;

        float dxr[4], dxi[4];
        {
            float vr[4], vi[4];
#pragma unroll
            for (int k1 = 0; k1 < 4; ++k1) {
                int qs = t + (k1 << 5);
                vr[k1] = T1r[qs * 33 + mm];
                vi[k1] = T1i[qs * 33 + mm];
            }
            fft_inv(vr, vi, T, t);
#pragma unroll
            for (int j = 0; j < 4; ++j) { dxr[j] = vr[j]; dxi[j] = vi[j]; }
        }

        float d2r_[4], d2i_[4];
        {
            float vr[4], vi[4];
#pragma unroll
            for (int k1 = 0; k1 < 4; ++k1) {
                int qs = t + (k1 << 5);
                vr[k1] = T2r[qs * 33 + mm];
                vi[k1] = T2i[qs * 33 + mm];
            }
            fft_inv(vr, vi, T, t);
#pragma unroll
            for (int j = 0; j < 4; ++j) { d2r_[j] = vr[j]; d2i_[j] = vi[j]; }
        }

        float oh[4], oa[4], op[4], ot[4], os[4];
#pragma unroll
        for (int j = 0; j < 4; ++j) {
            float Dr0 = dxr[j], Di0 = dxi[j];
            float d2r = d2r_[j], d2i = d2i_[j];

            float h = Dr0 * Dr0 + Di0 * Di0;
            bool valid = (h >= EPS2);
            float Dr = valid ? Dr0 : 1.0f;
            float Di = valid ? Di0 : 0.0f;
            float nD = valid ? h : 1.0f;
            float invnD = 1.0f / nD;

            float a2r = (dfcr * Dr + dfci * Di) * invnD;
            float a2i = (dfci * Dr - dfcr * Di) * invnD;

            float lnA = 0.0f, Phi = 0.0f;
            if (valid) {
                float la = 0.5f * __logf(a2r * a2r + a2i * a2i);
                lnA = fminf(3.0f, fmaxf(-3.0f, la));
                Phi = fatan2f(a2i, a2r);
            }

            float t1r = d2r * dfcr - d2i * dfci;
            float t1i = d2r * dfci + d2i * dfcr;
            float D2r = Dr * Dr - Di * Di;
            float D2i = 2.0f * Dr * Di;
            float invn2 = invnD * invnD;
            float anr = 0.5f * (t1r * D2r + t1i * D2i) * invn2 - hrr;
            float ani = 0.5f * (t1i * D2r - t1r * D2i) * invn2 - hri;

            float na = anr * anr + ani * ani;
            bool tm = valid && (na >= EPS2);
            float lnT = LN_EPS, Psi = 0.0f;
            if (tm) {
                float lt = 0.5f * __logf(na);
                lnT = fminf(3.0f, fmaxf(TR_MIN, lt));
                Psi = fatan2f(ani, anr);
            }

            oh[j] = h; oa[j] = lnA; op[j] = Phi; ot[j] = lnT; os[j] = Psi;
        }

        size_t base = (size_t)s * 16384 + (size_t)m * 128;
        __stcs(&((float4*)(out + base))[t],             *(float4*)oh);
        __stcs(&((float4*)(out + PLANE + base))[t],     *(float4*)oa);
        __stcs(&((float4*)(out + 2 * PLANE + base))[t], *(float4*)op);
        __stcs(&((float4*)(out + 3 * PLANE + base))[t], *(float4*)ot);
        __stcs(&((float4*)(out + 4 * PLANE + base))[t], *(float4*)os);
    }
}

extern "C" void kernel_launch(void* const* d_in, const int* in_sizes, int n_in,
                              void* d_out, int out_size)
{
    const float* x   = (const float*)d_in[0];
    const float* df  = (const float*)d_in[1];
    const float* d2f = (const float*)d_in[2];
    float* out = (float*)d_out;

    const int P1_SMEM = 2 * 128 * 128 * 4;   // 131072 B
    const int P2_SMEM = 4 * 4224 * 4;        // 67584 B

    cudaFuncSetAttribute(p1_kernel, cudaFuncAttributeMaxDynamicSharedMemorySize, P1_SMEM);
    cudaFuncSetAttribute(p2_kernel, cudaFuncAttributeMaxDynamicSharedMemorySize, P2_SMEM);

    p1_kernel<<<SLICES, 512, P1_SMEM>>>(x);
    p2_kernel<<<dim3(SLICES, 4), 512, P2_SMEM>>>(out, df, d2f);
}

// round 4
// speedup vs baseline: 1.5045x; 1.5045x over previous
#include <cuda_runtime.h>
#include <math.h>

#define NSIDE 128
#define SLICES 1024
#define PLANE 16777216ull   // 1024 * 128 * 128

// Scratch: Y1/Y2 stored [slice][qs][n-natural] as float2, qs = storage-permuted q
__device__ float2 g_Y1[SLICES * NSIDE * NSIDE];
__device__ float2 g_Y2[SLICES * NSIDE * NSIDE];

// ---------------------------------------------------------------------------
// Register/shuffle 128-pt FFT: 128 = 32 lanes x 4 regs.
// Input layout (P4):  thread t holds x[4t + j], j = reg 0..3
// Output layout (SP): thread b, reg k1 holds X[bitrev5(b) + 32*k1]
// Inverse consumes SP, produces P4, UNSCALED (x128); scaling folded by caller.
// ---------------------------------------------------------------------------
struct Tw {
    float w16r, w16i, w8r, w8i, w4r, w4i, w2r, w2i;
    float c1, s1, c2, s2, c3, s3;
};

__device__ __forceinline__ void stage_tw(int t, int h, float& cr, float& ci)
{
    if (t & h) {
        sincospif(-(float)(t & (h - 1)) / (float)h, &ci, &cr);
    } else { cr = 1.0f; ci = 0.0f; }
}

__device__ __forceinline__ void make_tw(Tw& T, int t)
{
    int br = __brev(t) >> 27;
    sincospif((float)br * (1.0f / 64.0f), &T.s1, &T.c1);
    sincospif((float)br * (1.0f / 32.0f), &T.s2, &T.c2);
    sincospif((float)(3 * br) * (1.0f / 64.0f), &T.s3, &T.c3);
    stage_tw(t, 16, T.w16r, T.w16i);
    stage_tw(t, 8,  T.w8r,  T.w8i);
    stage_tw(t, 4,  T.w4r,  T.w4i);
    stage_tw(t, 2,  T.w2r,  T.w2i);
}

__device__ __forceinline__ void cmulm(float& ar, float& ai, float br, float bi)
{
    float r = ar * br - ai * bi;
    ai = ar * bi + ai * br;
    ar = r;
}

template <int H>
__device__ __forceinline__ void lane_stage_f(float vr[4], float vi[4],
                                             float twr, float twi, int t)
{
    float e = (t & H) ? -1.0f : 1.0f;
#pragma unroll
    for (int r = 0; r < 4; ++r) {
        float pr = __shfl_xor_sync(0xffffffffu, vr[r], H);
        float pi = __shfl_xor_sync(0xffffffffu, vi[r], H);
        float ur = fmaf(e, vr[r], pr);
        float ui = fmaf(e, vi[r], pi);
        vr[r] = ur * twr - ui * twi;
        vi[r] = fmaf(ur, twi, ui * twr);
    }
}

__device__ __forceinline__ void lane_stage_f1(float vr[4], float vi[4], int t)
{
    float e = (t & 1) ? -1.0f : 1.0f;
#pragma unroll
    for (int r = 0; r < 4; ++r) {
        float pr = __shfl_xor_sync(0xffffffffu, vr[r], 1);
        float pi = __shfl_xor_sync(0xffffffffu, vi[r], 1);
        vr[r] = fmaf(e, vr[r], pr);
        vi[r] = fmaf(e, vi[r], pi);
    }
}

template <int H>
__device__ __forceinline__ void lane_stage_i(float vr[4], float vi[4],
                                             float twr, float twi, int t)
{
    float e = (t & H) ? -1.0f : 1.0f;
#pragma unroll
    for (int r = 0; r < 4; ++r) {
        float ar = fmaf(vi[r], twi, vr[r] * twr);
        float ai = vi[r] * twr - vr[r] * twi;
        float pr = __shfl_xor_sync(0xffffffffu, ar, H);
        float pi = __shfl_xor_sync(0xffffffffu, ai, H);
        vr[r] = fmaf(e, ar, pr);
        vi[r] = fmaf(e, ai, pi);
    }
}

__device__ __forceinline__ void lane_stage_i1(float vr[4], float vi[4], int t)
{
    float e = (t & 1) ? -1.0f : 1.0f;
#pragma unroll
    for (int r = 0; r < 4; ++r) {
        float pr = __shfl_xor_sync(0xffffffffu, vr[r], 1);
        float pi = __shfl_xor_sync(0xffffffffu, vi[r], 1);
        vr[r] = fmaf(e, vr[r], pr);
        vi[r] = fmaf(e, vi[r], pi);
    }
}

__device__ __forceinline__ void fft_fwd(float vr[4], float vi[4], const Tw& T, int t)
{
    lane_stage_f<16>(vr, vi, T.w16r, T.w16i, t);
    lane_stage_f<8>(vr, vi, T.w8r, T.w8i, t);
    lane_stage_f<4>(vr, vi, T.w4r, T.w4i, t);
    lane_stage_f<2>(vr, vi, T.w2r, T.w2i, t);
    lane_stage_f1(vr, vi, t);
    cmulm(vr[1], vi[1], T.c1, -T.s1);
    cmulm(vr[2], vi[2], T.c2, -T.s2);
    cmulm(vr[3], vi[3], T.c3, -T.s3);
    float s02r = vr[0] + vr[2], s02i = vi[0] + vi[2];
    float d02r = vr[0] - vr[2], d02i = vi[0] - vi[2];
    float s13r = vr[1] + vr[3], s13i = vi[1] + vi[3];
    float d13r = vr[1] - vr[3], d13i = vi[1] - vi[3];
    vr[0] = s02r + s13r; vi[0] = s02i + s13i;
    vr[2] = s02r - s13r; vi[2] = s02i - s13i;
    vr[1] = d02r + d13i; vi[1] = d02i - d13r;
    vr[3] = d02r - d13i; vi[3] = d02i + d13r;
}

__device__ __forceinline__ void fft_inv(float vr[4], float vi[4], const Tw& T, int t)
{
    float s02r = vr[0] + vr[2], s02i = vi[0] + vi[2];
    float d02r = vr[0] - vr[2], d02i = vi[0] - vi[2];
    float s13r = vr[1] + vr[3], s13i = vi[1] + vi[3];
    float d13r = vr[1] - vr[3], d13i = vi[1] - vi[3];
    vr[0] = s02r + s13r; vi[0] = s02i + s13i;
    vr[2] = s02r - s13r; vi[2] = s02i - s13i;
    vr[1] = d02r - d13i; vi[1] = d02i + d13r;
    vr[3] = d02r + d13i; vi[3] = d02i - d13r;
    cmulm(vr[1], vi[1], T.c1, T.s1);
    cmulm(vr[2], vi[2], T.c2, T.s2);
    cmulm(vr[3], vi[3], T.c3, T.s3);
    lane_stage_i1(vr, vi, t);
    lane_stage_i<2>(vr, vi, T.w2r, T.w2i, t);
    lane_stage_i<4>(vr, vi, T.w4r, T.w4i, t);
    lane_stage_i<8>(vr, vi, T.w8r, T.w8i, t);
    lane_stage_i<16>(vr, vi, T.w16r, T.w16i, t);
}

// Fast atan2: minimax odd poly, abs err ~1e-5 rad; sign/branch-cut identical
// to atan2f (copysign from y).
__device__ __forceinline__ float fatan2f(float y, float x)
{
    float ax = fabsf(x), ay = fabsf(y);
    float mx = fmaxf(ax, ay), mn = fminf(ax, ay);
    float a = __fdividef(mn, mx);
    float s = a * a;
    float p = -0.0117212f;
    p = fmaf(p, s, 0.05265332f);
    p = fmaf(p, s, -0.11643287f);
    p = fmaf(p, s, 0.19354346f);
    p = fmaf(p, s, -0.33262347f);
    p = fmaf(p, s, 0.99997726f);
    float r = p * a;
    if (ay > ax) r = 1.57079632679f - r;
    if (x < 0.0f) r = 3.14159265359f - r;
    return copysignf(r, y);
}

// ---------------------------------------------------------------------------
// P1: per slice. Row FFTs -> swizzled smem spectrum -> per storage-column:
// fwd FFT over m, W1/W2 multiply (bitrev spectral coords), 2x inverse,
// store Y1/Y2[s][qs][n] coalesced (plain float4 stores).
// ---------------------------------------------------------------------------
__global__ void __launch_bounds__(512) p1_kernel(const float* __restrict__ x)
{
    extern __shared__ float sm[];
    float* Fre = sm;
    float* Fim = sm + 16384;

    const int s   = blockIdx.x;
    const int tid = threadIdx.x;
    const int u   = tid >> 5;
    const int t   = tid & 31;

    Tw T;
    make_tw(T, t);

    const float4* xs = (const float4*)(x + (size_t)s * (NSIDE * NSIDE));

#pragma unroll 1
    for (int it = 0; it < 8; ++it) {
        int m = it * 16 + u;
        float4 v = xs[m * 32 + t];
        float vr[4] = { v.x, v.y, v.z, v.w };
        float vi[4] = { 0.0f, 0.0f, 0.0f, 0.0f };
        fft_fwd(vr, vi, T, t);
        int C = (m >> 2) & 31;
        int rowb = m << 7;
#pragma unroll
        for (int k1 = 0; k1 < 4; ++k1) {
            int sc = (t + (k1 << 5)) ^ C;
            Fre[rowb + sc] = vr[k1];
            Fim[rowb + sc] = vi[k1];
        }
    }
    __syncthreads();

    const float scale = 1.0f / 16384.0f;
    const int brv = __brev(t) >> 27;

#pragma unroll 1
    for (int it = 0; it < 8; ++it) {
        int qs = it * 16 + u;
        int q_idx = (__brev(qs & 31) >> 27) + (qs & 96);
        float kq = (q_idx < 64) ? (float)q_idx : (float)(q_idx - 128);

        float vr[4], vi[4];
#pragma unroll
        for (int j = 0; j < 4; ++j) {
            int p = 4 * t + j;
            int sc = qs ^ t;
            vr[j] = Fre[(p << 7) + sc];
            vi[j] = Fim[(p << 7) + sc];
        }
        fft_fwd(vr, vi, T, t);

        float fr[4], fi[4];
#pragma unroll
        for (int k1 = 0; k1 < 4; ++k1) { fr[k1] = vr[k1]; fi[k1] = vi[k1]; }

        // G1 = (i*kp - kq) * F * scale
#pragma unroll
        for (int k1 = 0; k1 < 4; ++k1) {
            int p_idx = brv + (k1 << 5);
            float kp = (p_idx < 64) ? (float)p_idx : (float)(p_idx - 128);
            float w1r = -kq * scale, w1i = kp * scale;
            vr[k1] = fr[k1] * w1r - fi[k1] * w1i;
            vi[k1] = fr[k1] * w1i + fi[k1] * w1r;
        }
        fft_inv(vr, vi, T, t);
        {
            float4* y = (float4*)(g_Y1 + ((size_t)s * NSIDE + qs) * NSIDE + 4 * t);
            y[0] = make_float4(vr[0], vi[0], vr[1], vi[1]);
            y[1] = make_float4(vr[2], vi[2], vr[3], vi[3]);
        }

        // G2 = ((kq^2 - kp^2) - i*2*kp*kq) * F * scale
#pragma unroll
        for (int k1 = 0; k1 < 4; ++k1) {
            int p_idx = brv + (k1 << 5);
            float kp = (p_idx < 64) ? (float)p_idx : (float)(p_idx - 128);
            float w2r = (kq * kq - kp * kp) * scale;
            float w2i = -2.0f * kp * kq * scale;
            vr[k1] = fr[k1] * w2r - fi[k1] * w2i;
            vi[k1] = fr[k1] * w2i + fi[k1] * w2r;
        }
        fft_inv(vr, vi, T, t);
        {
            float4* y = (float4*)(g_Y2 + ((size_t)s * NSIDE + qs) * NSIDE + 4 * t);
            y[0] = make_float4(vr[0], vi[0], vr[1], vi[1]);
            y[1] = make_float4(vr[2], vi[2], vr[3], vi[3]);
        }
    }
}

// ---------------------------------------------------------------------------
// P2: per (slice, 32-row tile). Load Y tiles coalesced (float2), transpose via
// stride-33 smem, inverse FFT over q (register/shuffle), fast fused epilogue.
// ---------------------------------------------------------------------------
__global__ void __launch_bounds__(512, 2) p2_kernel(float* __restrict__ out,
                                                    const float* __restrict__ df,
                                                    const float* __restrict__ d2f)
{
    extern __shared__ float sm[];
    float* T1r = sm;
    float* T1i = T1r + 4224;
    float* T2r = T1i + 4224;
    float* T2i = T2r + 4224;

    const int s    = blockIdx.x;
    const int m0   = blockIdx.y * 32;
    const int tid  = threadIdx.x;
    const int u    = tid >> 5;
    const int t    = tid & 31;

    Tw T;
    make_tw(T, t);

    const float2* y1 = g_Y1 + (size_t)s * (NSIDE * NSIDE);
    const float2* y2 = g_Y2 + (size_t)s * (NSIDE * NSIDE);
#pragma unroll
    for (int i = 0; i < 8; ++i) {
        int e  = i * 512 + tid;
        int q  = e >> 5;
        int mm = e & 31;
        float2 v1 = y1[q * NSIDE + m0 + mm];
        T1r[q * 33 + mm] = v1.x;
        T1i[q * 33 + mm] = v1.y;
        float2 v2 = y2[q * NSIDE + m0 + mm];
        T2r[q * 33 + mm] = v2.x;
        T2i[q * 33 + mm] = v2.y;
    }
    __syncthreads();

    const int c = s & 63;
    float df0 = df[2 * c], df1 = df[2 * c + 1];
    float ed  = expf(df0);
    float dfcr = ed * cosf(df1), dfci = ed * sinf(df1);
    float d20 = d2f[2 * c], d21 = d2f[2 * c + 1];
    float inv_nf = 0.5f / (dfcr * dfcr + dfci * dfci);
    float hrr = (d20 * dfcr + d21 * dfci) * inv_nf;
    float hri = (d21 * dfcr - d20 * dfci) * inv_nf;

    const float EPS2   = 1e-6f;
    const float LN_EPS = -6.9077552790f;
    const float TR_MIN = -2.5902671570f;

#pragma unroll 1
    for (int iter = 0; iter < 2; ++iter) {
        int mm = iter * 16 + u;
        int m  = m0 + mm;

        float dxr[4], dxi[4];
        {
            float vr[4], vi[4];
#pragma unroll
            for (int k1 = 0; k1 < 4; ++k1) {
                int qs = t + (k1 << 5);
                vr[k1] = T1r[qs * 33 + mm];
                vi[k1] = T1i[qs * 33 + mm];
            }
            fft_inv(vr, vi, T, t);
#pragma unroll
            for (int j = 0; j < 4; ++j) { dxr[j] = vr[j]; dxi[j] = vi[j]; }
        }

        float d2r_[4], d2i_[4];
        {
            float vr[4], vi[4];
#pragma unroll
            for (int k1 = 0; k1 < 4; ++k1) {
                int qs = t + (k1 << 5);
                vr[k1] = T2r[qs * 33 + mm];
                vi[k1] = T2i[qs * 33 + mm];
            }
            fft_inv(vr, vi, T, t);
#pragma unroll
            for (int j = 0; j < 4; ++j) { d2r_[j] = vr[j]; d2i_[j] = vi[j]; }
        }

        float oh[4], oa[4], op[4], ot[4], os[4];
#pragma unroll
        for (int j = 0; j < 4; ++j) {
            float Dr0 = dxr[j], Di0 = dxi[j];
            float d2r = d2r_[j], d2i = d2i_[j];

            float h = Dr0 * Dr0 + Di0 * Di0;
            bool valid = (h >= EPS2);
            float Dr = valid ? Dr0 : 1.0f;
            float Di = valid ? Di0 : 0.0f;
            float nD = valid ? h : 1.0f;
            float invnD = 1.0f / nD;

            float a2r = (dfcr * Dr + dfci * Di) * invnD;
            float a2i = (dfci * Dr - dfcr * Di) * invnD;

            float lnA = 0.0f, Phi = 0.0f;
            if (valid) {
                float la = 0.5f * __logf(a2r * a2r + a2i * a2i);
                lnA = fminf(3.0f, fmaxf(-3.0f, la));
                Phi = fatan2f(a2i, a2r);
            }

            float t1r = d2r * dfcr - d2i * dfci;
            float t1i = d2r * dfci + d2i * dfcr;
            float D2r = Dr * Dr - Di * Di;
            float D2i = 2.0f * Dr * Di;
            float invn2 = invnD * invnD;
            float anr = 0.5f * (t1r * D2r + t1i * D2i) * invn2 - hrr;
            float ani = 0.5f * (t1i * D2r - t1r * D2i) * invn2 - hri;

            float na = anr * anr + ani * ani;
            bool tm = valid && (na >= EPS2);
            float lnT = LN_EPS, Psi = 0.0f;
            if (tm) {
                float lt = 0.5f * __logf(na);
                lnT = fminf(3.0f, fmaxf(TR_MIN, lt));
                Psi = fatan2f(ani, anr);
            }

            oh[j] = h; oa[j] = lnA; op[j] = Phi; ot[j] = lnT; os[j] = Psi;
        }

        size_t base = (size_t)s * 16384 + (size_t)m * 128;
        ((float4*)(out + base))[t]             = *(float4*)oh;
        ((float4*)(out + PLANE + base))[t]     = *(float4*)oa;
        ((float4*)(out + 2 * PLANE + base))[t] = *(float4*)op;
        ((float4*)(out + 3 * PLANE + base))[t] = *(float4*)ot;
        ((float4*)(out + 4 * PLANE + base))[t] = *(float4*)os;
    }
}

extern "C" void kernel_launch(void* const* d_in, const int* in_sizes, int n_in,
                              void* d_out, int out_size)
{
    const float* x   = (const float*)d_in[0];
    const float* df  = (const float*)d_in[1];
    const float* d2f = (const float*)d_in[2];
    float* out = (float*)d_out;

    const int P1_SMEM = 2 * 128 * 128 * 4;   // 131072 B
    const int P2_SMEM = 4 * 4224 * 4;        // 67584 B

    cudaFuncSetAttribute(p1_kernel, cudaFuncAttributeMaxDynamicSharedMemorySize, P1_SMEM);
    cudaFuncSetAttribute(p2_kernel, cudaFuncAttributeMaxDynamicSharedMemorySize, P2_SMEM);

    p1_kernel<<<SLICES, 512, P1_SMEM>>>(x);
    p2_kernel<<<dim3(SLICES, 4), 512, P2_SMEM>>>(out, df, d2f);
}

// round 5
// speedup vs baseline: 1.6300x; 1.0834x over previous
#include <cuda_runtime.h>
#include <math.h>

#define NSIDE 128
#define SLICES 1024
#define PLANE 16777216ull   // 1024 * 128 * 128

// Scratch: Y1/Y2 stored [slice][qs][n-natural] as float2, qs = storage-permuted q
__device__ float2 g_Y1[SLICES * NSIDE * NSIDE];
__device__ float2 g_Y2[SLICES * NSIDE * NSIDE];

// ---------------------------------------------------------------------------
// Register/shuffle 128-pt FFT, batched NF-ways for ILP: 128 = 32 lanes x 4 regs.
// Input layout (P4):  thread t holds x[4t + j], j = reg 0..3
// Output layout (SP): thread b, reg k1 holds X[bitrev5(b) + 32*k1]
// Inverse consumes SP, produces P4, UNSCALED (x128); scaling folded by caller.
// ---------------------------------------------------------------------------
struct Tw {
    float w16r, w16i, w8r, w8i, w4r, w4i, w2r, w2i;
    float c1, s1, c2, s2, c3, s3;
};

__device__ __forceinline__ void stage_tw(int t, int h, float& cr, float& ci)
{
    if (t & h) {
        sincospif(-(float)(t & (h - 1)) / (float)h, &ci, &cr);
    } else { cr = 1.0f; ci = 0.0f; }
}

__device__ __forceinline__ void make_tw(Tw& T, int t)
{
    int br = __brev(t) >> 27;
    sincospif((float)br * (1.0f / 64.0f), &T.s1, &T.c1);
    sincospif((float)br * (1.0f / 32.0f), &T.s2, &T.c2);
    sincospif((float)(3 * br) * (1.0f / 64.0f), &T.s3, &T.c3);
    stage_tw(t, 16, T.w16r, T.w16i);
    stage_tw(t, 8,  T.w8r,  T.w8i);
    stage_tw(t, 4,  T.w4r,  T.w4i);
    stage_tw(t, 2,  T.w2r,  T.w2i);
}

__device__ __forceinline__ void cmulm(float& ar, float& ai, float br, float bi)
{
    float r = ar * br - ai * bi;
    ai = ar * bi + ai * br;
    ar = r;
}

template <int NF, int H>
__device__ __forceinline__ void lstage_f(float (&vr)[NF][4], float (&vi)[NF][4],
                                         float twr, float twi, int t)
{
    float e = (t & H) ? -1.0f : 1.0f;
    float pr[NF][4], pi[NF][4];
#pragma unroll
    for (int f = 0; f < NF; ++f)
#pragma unroll
        for (int r = 0; r < 4; ++r) {
            pr[f][r] = __shfl_xor_sync(0xffffffffu, vr[f][r], H);
            pi[f][r] = __shfl_xor_sync(0xffffffffu, vi[f][r], H);
        }
#pragma unroll
    for (int f = 0; f < NF; ++f)
#pragma unroll
        for (int r = 0; r < 4; ++r) {
            float ur = fmaf(e, vr[f][r], pr[f][r]);
            float ui = fmaf(e, vi[f][r], pi[f][r]);
            vr[f][r] = ur * twr - ui * twi;
            vi[f][r] = fmaf(ur, twi, ui * twr);
        }
}

template <int NF>
__device__ __forceinline__ void lstage_f1(float (&vr)[NF][4], float (&vi)[NF][4], int t)
{
    float e = (t & 1) ? -1.0f : 1.0f;
    float pr[NF][4], pi[NF][4];
#pragma unroll
    for (int f = 0; f < NF; ++f)
#pragma unroll
        for (int r = 0; r < 4; ++r) {
            pr[f][r] = __shfl_xor_sync(0xffffffffu, vr[f][r], 1);
            pi[f][r] = __shfl_xor_sync(0xffffffffu, vi[f][r], 1);
        }
#pragma unroll
    for (int f = 0; f < NF; ++f)
#pragma unroll
        for (int r = 0; r < 4; ++r) {
            vr[f][r] = fmaf(e, vr[f][r], pr[f][r]);
            vi[f][r] = fmaf(e, vi[f][r], pi[f][r]);
        }
}

template <int NF, int H>
__device__ __forceinline__ void lstage_i(float (&vr)[NF][4], float (&vi)[NF][4],
                                         float twr, float twi, int t)
{
    float e = (t & H) ? -1.0f : 1.0f;
    float ar[NF][4], ai[NF][4], pr[NF][4], pi[NF][4];
#pragma unroll
    for (int f = 0; f < NF; ++f)
#pragma unroll
        for (int r = 0; r < 4; ++r) {
            ar[f][r] = fmaf(vi[f][r], twi, vr[f][r] * twr);
            ai[f][r] = vi[f][r] * twr - vr[f][r] * twi;
        }
#pragma unroll
    for (int f = 0; f < NF; ++f)
#pragma unroll
        for (int r = 0; r < 4; ++r) {
            pr[f][r] = __shfl_xor_sync(0xffffffffu, ar[f][r], H);
            pi[f][r] = __shfl_xor_sync(0xffffffffu, ai[f][r], H);
        }
#pragma unroll
    for (int f = 0; f < NF; ++f)
#pragma unroll
        for (int r = 0; r < 4; ++r) {
            vr[f][r] = fmaf(e, ar[f][r], pr[f][r]);
            vi[f][r] = fmaf(e, ai[f][r], pi[f][r]);
        }
}

template <int NF>
__device__ __forceinline__ void lstage_i1(float (&vr)[NF][4], float (&vi)[NF][4], int t)
{
    float e = (t & 1) ? -1.0f : 1.0f;
    float pr[NF][4], pi[NF][4];
#pragma unroll
    for (int f = 0; f < NF; ++f)
#pragma unroll
        for (int r = 0; r < 4; ++r) {
            pr[f][r] = __shfl_xor_sync(0xffffffffu, vr[f][r], 1);
            pi[f][r] = __shfl_xor_sync(0xffffffffu, vi[f][r], 1);
        }
#pragma unroll
    for (int f = 0; f < NF; ++f)
#pragma unroll
        for (int r = 0; r < 4; ++r) {
            vr[f][r] = fmaf(e, vr[f][r], pr[f][r]);
            vi[f][r] = fmaf(e, vi[f][r], pi[f][r]);
        }
}

template <int NF>
__device__ __forceinline__ void fft_fwd_n(float (&vr)[NF][4], float (&vi)[NF][4],
                                          const Tw& T, int t)
{
    lstage_f<NF, 16>(vr, vi, T.w16r, T.w16i, t);
    lstage_f<NF, 8>(vr, vi, T.w8r, T.w8i, t);
    lstage_f<NF, 4>(vr, vi, T.w4r, T.w4i, t);
    lstage_f<NF, 2>(vr, vi, T.w2r, T.w2i, t);
    lstage_f1<NF>(vr, vi, t);
#pragma unroll
    for (int f = 0; f < NF; ++f) {
        cmulm(vr[f][1], vi[f][1], T.c1, -T.s1);
        cmulm(vr[f][2], vi[f][2], T.c2, -T.s2);
        cmulm(vr[f][3], vi[f][3], T.c3, -T.s3);
        float s02r = vr[f][0] + vr[f][2], s02i = vi[f][0] + vi[f][2];
        float d02r = vr[f][0] - vr[f][2], d02i = vi[f][0] - vi[f][2];
        float s13r = vr[f][1] + vr[f][3], s13i = vi[f][1] + vi[f][3];
        float d13r = vr[f][1] - vr[f][3], d13i = vi[f][1] - vi[f][3];
        vr[f][0] = s02r + s13r; vi[f][0] = s02i + s13i;
        vr[f][2] = s02r - s13r; vi[f][2] = s02i - s13i;
        vr[f][1] = d02r + d13i; vi[f][1] = d02i - d13r;
        vr[f][3] = d02r - d13i; vi[f][3] = d02i + d13r;
    }
}

template <int NF>
__device__ __forceinline__ void fft_inv_n(float (&vr)[NF][4], float (&vi)[NF][4],
                                          const Tw& T, int t)
{
#pragma unroll
    for (int f = 0; f < NF; ++f) {
        float s02r = vr[f][0] + vr[f][2], s02i = vi[f][0] + vi[f][2];
        float d02r = vr[f][0] - vr[f][2], d02i = vi[f][0] - vi[f][2];
        float s13r = vr[f][1] + vr[f][3], s13i = vi[f][1] + vi[f][3];
        float d13r = vr[f][1] - vr[f][3], d13i = vi[f][1] - vi[f][3];
        vr[f][0] = s02r + s13r; vi[f][0] = s02i + s13i;
        vr[f][2] = s02r - s13r; vi[f][2] = s02i - s13i;
        vr[f][1] = d02r - d13i; vi[f][1] = d02i + d13r;
        vr[f][3] = d02r + d13i; vi[f][3] = d02i - d13r;
        cmulm(vr[f][1], vi[f][1], T.c1, T.s1);
        cmulm(vr[f][2], vi[f][2], T.c2, T.s2);
        cmulm(vr[f][3], vi[f][3], T.c3, T.s3);
    }
    lstage_i1<NF>(vr, vi, t);
    lstage_i<NF, 2>(vr, vi, T.w2r, T.w2i, t);
    lstage_i<NF, 4>(vr, vi, T.w4r, T.w4i, t);
    lstage_i<NF, 8>(vr, vi, T.w8r, T.w8i, t);
    lstage_i<NF, 16>(vr, vi, T.w16r, T.w16i, t);
}

// Fast atan2: minimax odd poly, abs err ~1e-5 rad; sign/branch-cut identical
// to atan2f (copysign from y).
__device__ __forceinline__ float fatan2f(float y, float x)
{
    float ax = fabsf(x), ay = fabsf(y);
    float mx = fmaxf(ax, ay), mn = fminf(ax, ay);
    float a = __fdividef(mn, mx);
    float s = a * a;
    float p = -0.0117212f;
    p = fmaf(p, s, 0.05265332f);
    p = fmaf(p, s, -0.11643287f);
    p = fmaf(p, s, 0.19354346f);
    p = fmaf(p, s, -0.33262347f);
    p = fmaf(p, s, 0.99997726f);
    float r = p * a;
    if (ay > ax) r = 1.57079632679f - r;
    if (x < 0.0f) r = 3.14159265359f - r;
    return copysignf(r, y);
}

// ---------------------------------------------------------------------------
// P1: per slice. Row FFTs (2-way batched) -> swizzled smem spectrum ->
// per column pair: fwd FFT (2-way), W1/W2 multiply, 4-way batched inverse,
// store Y1/Y2[s][qs][n] coalesced.
// ---------------------------------------------------------------------------
__global__ void __launch_bounds__(512) p1_kernel(const float* __restrict__ x)
{
    extern __shared__ float sm[];
    float* Fre = sm;
    float* Fim = sm + 16384;

    const int s   = blockIdx.x;
    const int tid = threadIdx.x;
    const int u   = tid >> 5;
    const int t   = tid & 31;

    Tw T;
    make_tw(T, t);

    const float4* xs = (const float4*)(x + (size_t)s * (NSIDE * NSIDE));

#pragma unroll 1
    for (int it = 0; it < 4; ++it) {
        int m1 = it * 32 + u;
        int m2 = m1 + 16;
        float vr[2][4], vi[2][4];
        float4 a = xs[m1 * 32 + t];
        float4 b = xs[m2 * 32 + t];
        vr[0][0] = a.x; vr[0][1] = a.y; vr[0][2] = a.z; vr[0][3] = a.w;
        vr[1][0] = b.x; vr[1][1] = b.y; vr[1][2] = b.z; vr[1][3] = b.w;
#pragma unroll
        for (int j = 0; j < 4; ++j) { vi[0][j] = 0.0f; vi[1][j] = 0.0f; }
        fft_fwd_n<2>(vr, vi, T, t);
        int C1 = (m1 >> 2) & 31, C2 = (m2 >> 2) & 31;
#pragma unroll
        for (int k1 = 0; k1 < 4; ++k1) {
            int i1 = (t + (k1 << 5)) ^ C1;
            Fre[(m1 << 7) + i1] = vr[0][k1];
            Fim[(m1 << 7) + i1] = vi[0][k1];
            int i2 = (t + (k1 << 5)) ^ C2;
            Fre[(m2 << 7) + i2] = vr[1][k1];
            Fim[(m2 << 7) + i2] = vi[1][k1];
        }
    }
    __syncthreads();

    const float scale = 1.0f / 16384.0f;
    const int brv = __brev(t) >> 27;

#pragma unroll 1
    for (int it = 0; it < 4; ++it) {
        int qs1 = it * 32 + u;
        int qs2 = qs1 + 16;
        int qi1 = (__brev(qs1 & 31) >> 27) + (qs1 & 96);
        int qi2 = (__brev(qs2 & 31) >> 27) + (qs2 & 96);
        float kq1 = (qi1 < 64) ? (float)qi1 : (float)(qi1 - 128);
        float kq2 = (qi2 < 64) ? (float)qi2 : (float)(qi2 - 128);

        float fvr[2][4], fvi[2][4];
#pragma unroll
        for (int j = 0; j < 4; ++j) {
            int p = 4 * t + j;
            int sc1 = qs1 ^ t, sc2 = qs2 ^ t;
            fvr[0][j] = Fre[(p << 7) + sc1];
            fvi[0][j] = Fim[(p << 7) + sc1];
            fvr[1][j] = Fre[(p << 7) + sc2];
            fvi[1][j] = Fim[(p << 7) + sc2];
        }
        fft_fwd_n<2>(fvr, fvi, T, t);

        // Build 4 multiplied spectra: [0]=W1*Fa, [1]=W2*Fa, [2]=W1*Fb, [3]=W2*Fb
        float gr[4][4], gi[4][4];
#pragma unroll
        for (int k1 = 0; k1 < 4; ++k1) {
            int p_idx = brv + (k1 << 5);
            float kp = (p_idx < 64) ? (float)p_idx : (float)(p_idx - 128);
            float w1r = -kq1 * scale, w1i = kp * scale;
            gr[0][k1] = fvr[0][k1] * w1r - fvi[0][k1] * w1i;
            gi[0][k1] = fvr[0][k1] * w1i + fvi[0][k1] * w1r;
            float w2r = (kq1 * kq1 - kp * kp) * scale;
            float w2i = -2.0f * kp * kq1 * scale;
            gr[1][k1] = fvr[0][k1] * w2r - fvi[0][k1] * w2i;
            gi[1][k1] = fvr[0][k1] * w2i + fvi[0][k1] * w2r;
            float u1r = -kq2 * scale, u1i = kp * scale;
            gr[2][k1] = fvr[1][k1] * u1r - fvi[1][k1] * u1i;
            gi[2][k1] = fvr[1][k1] * u1i + fvi[1][k1] * u1r;
            float u2r = (kq2 * kq2 - kp * kp) * scale;
            float u2i = -2.0f * kp * kq2 * scale;
            gr[3][k1] = fvr[1][k1] * u2r - fvi[1][k1] * u2i;
            gi[3][k1] = fvr[1][k1] * u2i + fvi[1][k1] * u2r;
        }
        fft_inv_n<4>(gr, gi, T, t);

        float4* y;
        y = (float4*)(g_Y1 + ((size_t)s * NSIDE + qs1) * NSIDE + 4 * t);
        y[0] = make_float4(gr[0][0], gi[0][0], gr[0][1], gi[0][1]);
        y[1] = make_float4(gr[0][2], gi[0][2], gr[0][3], gi[0][3]);
        y = (float4*)(g_Y2 + ((size_t)s * NSIDE + qs1) * NSIDE + 4 * t);
        y[0] = make_float4(gr[1][0], gi[1][0], gr[1][1], gi[1][1]);
        y[1] = make_float4(gr[1][2], gi[1][2], gr[1][3], gi[1][3]);
        y = (float4*)(g_Y1 + ((size_t)s * NSIDE + qs2) * NSIDE + 4 * t);
        y[0] = make_float4(gr[2][0], gi[2][0], gr[2][1], gi[2][1]);
        y[1] = make_float4(gr[2][2], gi[2][2], gr[2][3], gi[2][3]);
        y = (float4*)(g_Y2 + ((size_t)s * NSIDE + qs2) * NSIDE + 4 * t);
        y[0] = make_float4(gr[3][0], gi[3][0], gr[3][1], gi[3][1]);
        y[1] = make_float4(gr[3][2], gi[3][2], gr[3][3], gi[3][3]);
    }
}

// ---------------------------------------------------------------------------
// P2: per (slice, 32-row tile). float4 tile loads, stride-33 smem transpose,
// inverse FFT over q (register/shuffle), fused fast epilogue.
// ---------------------------------------------------------------------------
__global__ void __launch_bounds__(512, 2) p2_kernel(float* __restrict__ out,
                                                    const float* __restrict__ df,
                                                    const float* __restrict__ d2f)
{
    extern __shared__ float sm[];
    float* T1r = sm;
    float* T1i = T1r + 4224;
    float* T2r = T1i + 4224;
    float* T2i = T2r + 4224;

    const int s    = blockIdx.x;
    const int m0   = blockIdx.y * 32;
    const int tid  = threadIdx.x;
    const int u    = tid >> 5;
    const int t    = tid & 31;

    Tw T;
    make_tw(T, t);

    // float4 = 2 adjacent pixels (float2 each); plain loads (no .cs!)
    const float4* y1v = (const float4*)(g_Y1 + (size_t)s * (NSIDE * NSIDE));
    const float4* y2v = (const float4*)(g_Y2 + (size_t)s * (NSIDE * NSIDE));
    const int mb = blockIdx.y * 16;   // m0/2 in float4 units

#pragma unroll
    for (int i = 0; i < 4; ++i) {
        int e  = i * 512 + tid;
        int q  = e >> 4;          // 0..127
        int mp = e & 15;          // pixel-pair index 0..15
        float4 v1 = y1v[q * 64 + mb + mp];
        T1r[q * 33 + 2 * mp]     = v1.x;
        T1i[q * 33 + 2 * mp]     = v1.y;
        T1r[q * 33 + 2 * mp + 1] = v1.z;
        T1i[q * 33 + 2 * mp + 1] = v1.w;
        float4 v2 = y2v[q * 64 + mb + mp];
        T2r[q * 33 + 2 * mp]     = v2.x;
        T2i[q * 33 + 2 * mp]     = v2.y;
        T2r[q * 33 + 2 * mp + 1] = v2.z;
        T2i[q * 33 + 2 * mp + 1] = v2.w;
    }
    __syncthreads();

    const int c = s & 63;
    float df0 = df[2 * c], df1 = df[2 * c + 1];
    float ed  = expf(df0);
    float dfcr = ed * cosf(df1), dfci = ed * sinf(df1);
    float d20 = d2f[2 * c], d21 = d2f[2 * c + 1];
    float inv_nf = 0.5f / (dfcr * dfcr + dfci * dfci);
    float hrr = (d20 * dfcr + d21 * dfci) * inv_nf;
    float hri = (d21 * dfcr - d20 * dfci) * inv_nf;

    const float EPS2   = 1e-6f;
    const float LN_EPS = -6.9077552790f;
    const float TR_MIN = -2.5902671570f;

#pragma unroll 1
    for (int iter = 0; iter < 2; ++iter) {
        int mm = iter * 16 + u;
        int m  = m0 + mm;

        float dxr[1][4], dxi[1][4];
#pragma unroll
        for (int k1 = 0; k1 < 4; ++k1) {
            int qs = t + (k1 << 5);
            dxr[0][k1] = T1r[qs * 33 + mm];
            dxi[0][k1] = T1i[qs * 33 + mm];
        }
        fft_inv_n<1>(dxr, dxi, T, t);

        float d2r_[1][4], d2i_[1][4];
#pragma unroll
        for (int k1 = 0; k1 < 4; ++k1) {
            int qs = t + (k1 << 5);
            d2r_[0][k1] = T2r[qs * 33 + mm];
            d2i_[0][k1] = T2i[qs * 33 + mm];
        }
        fft_inv_n<1>(d2r_, d2i_, T, t);

        float oh[4], oa[4], op[4], ot[4], os[4];
#pragma unroll
        for (int j = 0; j < 4; ++j) {
            float Dr0 = dxr[0][j], Di0 = dxi[0][j];
            float d2r = d2r_[0][j], d2i = d2i_[0][j];

            float h = Dr0 * Dr0 + Di0 * Di0;
            bool valid = (h >= EPS2);
            float Dr = valid ? Dr0 : 1.0f;
            float Di = valid ? Di0 : 0.0f;
            float nD = valid ? h : 1.0f;

            float lnA = 0.0f, Phi = 0.0f;
            if (valid) {
                // ln|a2| = ln|dfc| - ln|D| = df0 - 0.5*ln h
                float la = df0 - 0.5f * __logf(h);
                lnA = fminf(3.0f, fmaxf(-3.0f, la));
                // angle(a2) = angle(dfc * conj(D)) — scale-invariant
                float a2r = dfcr * Dr + dfci * Di;
                float a2i = dfci * Dr - dfcr * Di;
                Phi = fatan2f(a2i, a2r);
            }

            float t1r = d2r * dfcr - d2i * dfci;
            float t1i = d2r * dfci + d2i * dfcr;
            float D2r = Dr * Dr - Di * Di;
            float D2i = 2.0f * Dr * Di;
            float inv2h = 0.5f * __fdividef(1.0f, nD * nD);
            float anr = (t1r * D2r + t1i * D2i) * inv2h - hrr;
            float ani = (t1i * D2r - t1r * D2i) * inv2h - hri;

            float na = anr * anr + ani * ani;
            bool tm = valid && (na >= EPS2);
            float lnT = LN_EPS, Psi = 0.0f;
            if (tm) {
                float lt = 0.5f * __logf(na);
                lnT = fminf(3.0f, fmaxf(TR_MIN, lt));
                Psi = fatan2f(ani, anr);
            }

            oh[j] = h; oa[j] = lnA; op[j] = Phi; ot[j] = lnT; os[j] = Psi;
        }

        size_t base = (size_t)s * 16384 + (size_t)m * 128;
        ((float4*)(out + base))[t]             = *(float4*)oh;
        ((float4*)(out + PLANE + base))[t]     = *(float4*)oa;
        ((float4*)(out + 2 * PLANE + base))[t] = *(float4*)op;
        ((float4*)(out + 3 * PLANE + base))[t] = *(float4*)ot;
        ((float4*)(out + 4 * PLANE + base))[t] = *(float4*)os;
    }
}

extern "C" void kernel_launch(void* const* d_in, const int* in_sizes, int n_in,
                              void* d_out, int out_size)
{
    const float* x   = (const float*)d_in[0];
    const float* df  = (const float*)d_in[1];
    const float* d2f = (const float*)d_in[2];
    float* out = (float*)d_out;

    const int P1_SMEM = 2 * 128 * 128 * 4;   // 131072 B
    const int P2_SMEM = 4 * 4224 * 4;        // 67584 B

    cudaFuncSetAttribute(p1_kernel, cudaFuncAttributeMaxDynamicSharedMemorySize, P1_SMEM);
    cudaFuncSetAttribute(p2_kernel, cudaFuncAttributeMaxDynamicSharedMemorySize, P2_SMEM);

    p1_kernel<<<SLICES, 512, P1_SMEM>>>(x);
    p2_kernel<<<dim3(SLICES, 4), 512, P2_SMEM>>>(out, df, d2f);
}

// round 7
// speedup vs baseline: 1.6533x; 1.0143x over previous
#include <cuda_runtime.h>
#include <math.h>

#define NSIDE 128
#define SLICES 1024
#define PLANE 16777216ull   // 1024 * 128 * 128

// Scratch: Y1/Y2 stored [slice][qs][n-natural] as float2, qs = storage-permuted q
__device__ float2 g_Y1[SLICES * NSIDE * NSIDE];
__device__ float2 g_Y2[SLICES * NSIDE * NSIDE];

// ---------------------------------------------------------------------------
// Register/shuffle 128-pt FFT, batched NF-ways for ILP: 128 = 32 lanes x 4 regs.
// Input layout (P4):  thread t holds x[4t + j], j = reg 0..3
// Output layout (SP): thread b, reg k1 holds X[bitrev5(b) + 32*k1]
// Inverse consumes SP, produces P4, UNSCALED (x128); scaling folded by caller.
// ---------------------------------------------------------------------------
struct Tw {
    float w16r, w16i, w8r, w8i, w4r, w4i, w2r, w2i;
    float c1, s1, c2, s2, c3, s3;
};

__device__ __forceinline__ void stage_tw(int t, int h, float& cr, float& ci)
{
    if (t & h) {
        sincospif(-(float)(t & (h - 1)) / (float)h, &ci, &cr);
    } else { cr = 1.0f; ci = 0.0f; }
}

__device__ __forceinline__ void make_tw(Tw& T, int t)
{
    int br = __brev(t) >> 27;
    sincospif((float)br * (1.0f / 64.0f), &T.s1, &T.c1);
    sincospif((float)br * (1.0f / 32.0f), &T.s2, &T.c2);
    sincospif((float)(3 * br) * (1.0f / 64.0f), &T.s3, &T.c3);
    stage_tw(t, 16, T.w16r, T.w16i);
    stage_tw(t, 8,  T.w8r,  T.w8i);
    stage_tw(t, 4,  T.w4r,  T.w4i);
    stage_tw(t, 2,  T.w2r,  T.w2i);
}

__device__ __forceinline__ void cmulm(float& ar, float& ai, float br, float bi)
{
    float r = ar * br - ai * bi;
    ai = ar * bi + ai * br;
    ar = r;
}

template <int NF, int H>
__device__ __forceinline__ void lstage_f(float (&vr)[NF][4], float (&vi)[NF][4],
                                         float twr, float twi, int t)
{
    float e = (t & H) ? -1.0f : 1.0f;
    float pr[NF][4], pi[NF][4];
#pragma unroll
    for (int f = 0; f < NF; ++f)
#pragma unroll
        for (int r = 0; r < 4; ++r) {
            pr[f][r] = __shfl_xor_sync(0xffffffffu, vr[f][r], H);
            pi[f][r] = __shfl_xor_sync(0xffffffffu, vi[f][r], H);
        }
#pragma unroll
    for (int f = 0; f < NF; ++f)
#pragma unroll
        for (int r = 0; r < 4; ++r) {
            float ur = fmaf(e, vr[f][r], pr[f][r]);
            float ui = fmaf(e, vi[f][r], pi[f][r]);
            vr[f][r] = ur * twr - ui * twi;
            vi[f][r] = fmaf(ur, twi, ui * twr);
        }
}

template <int NF>
__device__ __forceinline__ void lstage_f1(float (&vr)[NF][4], float (&vi)[NF][4], int t)
{
    float e = (t & 1) ? -1.0f : 1.0f;
    float pr[NF][4], pi[NF][4];
#pragma unroll
    for (int f = 0; f < NF; ++f)
#pragma unroll
        for (int r = 0; r < 4; ++r) {
            pr[f][r] = __shfl_xor_sync(0xffffffffu, vr[f][r], 1);
            pi[f][r] = __shfl_xor_sync(0xffffffffu, vi[f][r], 1);
        }
#pragma unroll
    for (int f = 0; f < NF; ++f)
#pragma unroll
        for (int r = 0; r < 4; ++r) {
            vr[f][r] = fmaf(e, vr[f][r], pr[f][r]);
            vi[f][r] = fmaf(e, vi[f][r], pi[f][r]);
        }
}

template <int NF, int H>
__device__ __forceinline__ void lstage_i(float (&vr)[NF][4], float (&vi)[NF][4],
                                         float twr, float twi, int t)
{
    float e = (t & H) ? -1.0f : 1.0f;
    float ar[NF][4], ai[NF][4], pr[NF][4], pi[NF][4];
#pragma unroll
    for (int f = 0; f < NF; ++f)
#pragma unroll
        for (int r = 0; r < 4; ++r) {
            ar[f][r] = fmaf(vi[f][r], twi, vr[f][r] * twr);
            ai[f][r] = vi[f][r] * twr - vr[f][r] * twi;
        }
#pragma unroll
    for (int f = 0; f < NF; ++f)
#pragma unroll
        for (int r = 0; r < 4; ++r) {
            pr[f][r] = __shfl_xor_sync(0xffffffffu, ar[f][r], H);
            pi[f][r] = __shfl_xor_sync(0xffffffffu, ai[f][r], H);
        }
#pragma unroll
    for (int f = 0; f < NF; ++f)
#pragma unroll
        for (int r = 0; r < 4; ++r) {
            vr[f][r] = fmaf(e, ar[f][r], pr[f][r]);
            vi[f][r] = fmaf(e, ai[f][r], pi[f][r]);
        }
}

template <int NF>
__device__ __forceinline__ void lstage_i1(float (&vr)[NF][4], float (&vi)[NF][4], int t)
{
    float e = (t & 1) ? -1.0f : 1.0f;
    float pr[NF][4], pi[NF][4];
#pragma unroll
    for (int f = 0; f < NF; ++f)
#pragma unroll
        for (int r = 0; r < 4; ++r) {
            pr[f][r] = __shfl_xor_sync(0xffffffffu, vr[f][r], 1);
            pi[f][r] = __shfl_xor_sync(0xffffffffu, vi[f][r], 1);
        }
#pragma unroll
    for (int f = 0; f < NF; ++f)
#pragma unroll
        for (int r = 0; r < 4; ++r) {
            vr[f][r] = fmaf(e, vr[f][r], pr[f][r]);
            vi[f][r] = fmaf(e, vi[f][r], pi[f][r]);
        }
}

template <int NF>
__device__ __forceinline__ void fft_fwd_n(float (&vr)[NF][4], float (&vi)[NF][4],
                                          const Tw& T, int t)
{
    lstage_f<NF, 16>(vr, vi, T.w16r, T.w16i, t);
    lstage_f<NF, 8>(vr, vi, T.w8r, T.w8i, t);
    lstage_f<NF, 4>(vr, vi, T.w4r, T.w4i, t);
    lstage_f<NF, 2>(vr, vi, T.w2r, T.w2i, t);
    lstage_f1<NF>(vr, vi, t);
#pragma unroll
    for (int f = 0; f < NF; ++f) {
        cmulm(vr[f][1], vi[f][1], T.c1, -T.s1);
        cmulm(vr[f][2], vi[f][2], T.c2, -T.s2);
        cmulm(vr[f][3], vi[f][3], T.c3, -T.s3);
        float s02r = vr[f][0] + vr[f][2], s02i = vi[f][0] + vi[f][2];
        float d02r = vr[f][0] - vr[f][2], d02i = vi[f][0] - vi[f][2];
        float s13r = vr[f][1] + vr[f][3], s13i = vi[f][1] + vi[f][3];
        float d13r = vr[f][1] - vr[f][3], d13i = vi[f][1] - vi[f][3];
        vr[f][0] = s02r + s13r; vi[f][0] = s02i + s13i;
        vr[f][2] = s02r - s13r; vi[f][2] = s02i - s13i;
        vr[f][1] = d02r + d13i; vi[f][1] = d02i - d13r;
        vr[f][3] = d02r - d13i; vi[f][3] = d02i + d13r;
    }
}

template <int NF>
__device__ __forceinline__ void fft_inv_n(float (&vr)[NF][4], float (&vi)[NF][4],
                                          const Tw& T, int t)
{
#pragma unroll
    for (int f = 0; f < NF; ++f) {
        float s02r = vr[f][0] + vr[f][2], s02i = vi[f][0] + vi[f][2];
        float d02r = vr[f][0] - vr[f][2], d02i = vi[f][0] - vi[f][2];
        float s13r = vr[f][1] + vr[f][3], s13i = vi[f][1] + vi[f][3];
        float d13r = vr[f][1] - vr[f][3], d13i = vi[f][1] - vi[f][3];
        vr[f][0] = s02r + s13r; vi[f][0] = s02i + s13i;
        vr[f][2] = s02r - s13r; vi[f][2] = s02i - s13i;
        vr[f][1] = d02r - d13i; vi[f][1] = d02i + d13r;
        vr[f][3] = d02r + d13i; vi[f][3] = d02i - d13r;
        cmulm(vr[f][1], vi[f][1], T.c1, T.s1);
        cmulm(vr[f][2], vi[f][2], T.c2, T.s2);
        cmulm(vr[f][3], vi[f][3], T.c3, T.s3);
    }
    lstage_i1<NF>(vr, vi, t);
    lstage_i<NF, 2>(vr, vi, T.w2r, T.w2i, t);
    lstage_i<NF, 4>(vr, vi, T.w4r, T.w4i, t);
    lstage_i<NF, 8>(vr, vi, T.w8r, T.w8i, t);
    lstage_i<NF, 16>(vr, vi, T.w16r, T.w16i, t);
}

// Fast atan2: minimax odd poly, abs err ~1e-5 rad; sign/branch-cut identical
// to atan2f (copysign from y).
__device__ __forceinline__ float fatan2f(float y, float x)
{
    float ax = fabsf(x), ay = fabsf(y);
    float mx = fmaxf(ax, ay), mn = fminf(ax, ay);
    float a = __fdividef(mn, mx);
    float s = a * a;
    float p = -0.0117212f;
    p = fmaf(p, s, 0.05265332f);
    p = fmaf(p, s, -0.11643287f);
    p = fmaf(p, s, 0.19354346f);
    p = fmaf(p, s, -0.33262347f);
    p = fmaf(p, s, 0.99997726f);
    float r = p * a;
    if (ay > ax) r = 1.57079632679f - r;
    if (x < 0.0f) r = 3.14159265359f - r;
    return copysignf(r, y);
}

// storage column of spectral index kq (0..127): brev5 within 32-groups
__device__ __forceinline__ int st_of_kq(int kq)
{
    return (int)(__brev((unsigned)(kq & 31)) >> 27) + (kq & 96);
}

// ---------------------------------------------------------------------------
// P1: per slice, exploiting real input.
// Row phase: 64 packed complex FFTs (two real rows each), Hermitian split,
//   store spectrum columns kq<=64 only.
// Column phase: 64 units = 63 mirror pairs + special {0,64}. Each unit:
//   1 fwd FFT over m, build G1/G2 for +kq and -kq, 4-way batched inverse,
//   write 4 output columns (mirror columns conjugated).
// Nyquist fix: mirror multipliers need kp_eff = +64 (not -64) at p_idx==64.
// ---------------------------------------------------------------------------
__global__ void __launch_bounds__(512) p1_kernel(const float* __restrict__ x)
{
    extern __shared__ float sm[];
    float* Fre = sm;            // [m][sc] stride 128, swizzled col ^ ((m>>2)&31)
    float* Fim = sm + 16384;

    const int s   = blockIdx.x;
    const int tid = threadIdx.x;
    const int u   = tid >> 5;
    const int t   = tid & 31;

    Tw T;
    make_tw(T, t);
    const int r5 = __brev(t) >> 27;
    const int tP = (t == 0) ? 0 : (int)(__brev((unsigned)(32 - r5)) >> 27);

    const float4* xs = (const float4*)(x + (size_t)s * (NSIDE * NSIDE));

    // ---- row phase: 2 iterations x 2 packed pairs (NF=2) ----
#pragma unroll 1
    for (int it = 0; it < 2; ++it) {
        int pr0 = it * 32 + u;
        int pr1 = pr0 + 16;
        float vr[2][4], vi[2][4];
        {
            float4 a = xs[(2 * pr0) * 32 + t];
            float4 b = xs[(2 * pr0 + 1) * 32 + t];
            vr[0][0] = a.x; vr[0][1] = a.y; vr[0][2] = a.z; vr[0][3] = a.w;
            vi[0][0] = b.x; vi[0][1] = b.y; vi[0][2] = b.z; vi[0][3] = b.w;
            float4 c = xs[(2 * pr1) * 32 + t];
            float4 d = xs[(2 * pr1 + 1) * 32 + t];
            vr[1][0] = c.x; vr[1][1] = c.y; vr[1][2] = c.z; vr[1][3] = c.w;
            vi[1][0] = d.x; vi[1][1] = d.y; vi[1][2] = d.z; vi[1][3] = d.w;
        }
        fft_fwd_n<2>(vr, vi, T, t);

#pragma unroll
        for (int f = 0; f < 2; ++f) {
            int m1 = 2 * (f == 0 ? pr0 : pr1);
            int m2 = m1 + 1;
            int C  = (m1 >> 2) & 31;     // m1 even -> same key for m2
            float Znr[4], Zni[4];
#pragma unroll
            for (int k1 = 0; k1 < 4; ++k1) {
                Znr[k1] = __shfl_sync(0xffffffffu, vr[f][3 - k1], tP);
                Zni[k1] = __shfl_sync(0xffffffffu, vi[f][3 - k1], tP);
            }
            if (t == 0) {
                Znr[0] = vr[f][0]; Zni[0] = vi[f][0];
                Znr[1] = vr[f][3]; Zni[1] = vi[f][3];
                Znr[2] = vr[f][2]; Zni[2] = vi[f][2];
                Znr[3] = vr[f][1]; Zni[3] = vi[f][1];
            }
#pragma unroll
            for (int k1 = 0; k1 < 3; ++k1) {
                if (k1 < 2 || t == 0) {
                    float Far = 0.5f * (vr[f][k1] + Znr[k1]);
                    float Fai = 0.5f * (vi[f][k1] - Zni[k1]);
                    float Fbr = 0.5f * (vi[f][k1] + Zni[k1]);
                    float Fbi = 0.5f * (Znr[k1] - vr[f][k1]);
                    int col = (t + (k1 << 5)) ^ C;
                    Fre[(m1 << 7) + col] = Far;
                    Fim[(m1 << 7) + col] = Fai;
                    Fre[(m2 << 7) + col] = Fbr;
                    Fim[(m2 << 7) + col] = Fbi;
                }
            }
        }
    }
    __syncthreads();

    const float scale = 1.0f / 16384.0f;

    // ---- column phase: 4 iterations, 1 unit per warp ----
#pragma unroll 1
    for (int it = 0; it < 4; ++it) {
        int u_id = it * 16 + u;
        float gr[4][4], gi[4][4];
        int qsP, qsM;
        bool mirror_conj;

        if (u_id < 63) {
            int kq = u_id + 1;             // 1..63
            qsP = st_of_kq(kq);
            qsM = st_of_kq(128 - kq);
            mirror_conj = true;

            float fvr[1][4], fvi[1][4];
#pragma unroll
            for (int j = 0; j < 4; ++j) {
                int p = 4 * t + j;
                int sc = qsP ^ t;
                fvr[0][j] = Fre[(p << 7) + sc];
                fvi[0][j] = Fim[(p << 7) + sc];
            }
            fft_fwd_n<1>(fvr, fvi, T, t);

            float kqs = (float)kq * scale;
#pragma unroll
            for (int k1 = 0; k1 < 4; ++k1) {
                int p_idx = r5 + (k1 << 5);
                float kp  = (p_idx < 64) ? (float)p_idx : (float)(p_idx - 128);
                // Nyquist: index 64 is self-negating; mirror multipliers need
                // kp_eff = -decode(64) = +64 there.
                float sgnM = (p_idx == 64) ? -1.0f : 1.0f;
                float kps = kp * scale;
                float Fr = fvr[0][k1], Fi = fvi[0][k1];
                float a = kqs * Fr, b = kps * Fi, c = kps * Fr, d = kqs * Fi;
                gr[0][k1] = -a - b;            gi[0][k1] = c - d;        // G1(+kq)
                gr[1][k1] =  a - sgnM * b;     gi[1][k1] = sgnM * c + d; // G1(-kq), conj at store
                float A = ((float)kq * (float)kq - kp * kp) * scale;
                float B = 2.0f * kp * kqs;
                float Bm = sgnM * B;
                gr[2][k1] = fmaf(A, Fr,  B * Fi);        // G2(+kq)
                gi[2][k1] = fmaf(A, Fi, -B * Fr);
                gr[3][k1] = fmaf(A, Fr, -Bm * Fi);       // G2(-kq), conj at store
                gi[3][k1] = fmaf(A, Fi,  Bm * Fr);
            }
        } else {
            // special unit: spectral columns 0 (storage 0) and 64 (storage 64)
            qsP = 0; qsM = 64;
            mirror_conj = false;

            float fvr[2][4], fvi[2][4];
#pragma unroll
            for (int j = 0; j < 4; ++j) {
                int p = 4 * t + j;
                fvr[0][j] = Fre[(p << 7) + (0 ^ t)];
                fvi[0][j] = Fim[(p << 7) + (0 ^ t)];
                fvr[1][j] = Fre[(p << 7) + (64 ^ t)];
                fvi[1][j] = Fim[(p << 7) + (64 ^ t)];
            }
            fft_fwd_n<2>(fvr, fvi, T, t);

#pragma unroll
            for (int k1 = 0; k1 < 4; ++k1) {
                int p_idx = r5 + (k1 << 5);
                float kp  = (p_idx < 64) ? (float)p_idx : (float)(p_idx - 128);
                float kps = kp * scale;
                // col 0: W1 = (0, kp*sc); W2 = (-kp^2*sc, 0)
                gr[0][k1] = -fvi[0][k1] * kps;
                gi[0][k1] =  fvr[0][k1] * kps;
                float A0 = -kp * kps;
                gr[2][k1] = A0 * fvr[0][k1];
                gi[2][k1] = A0 * fvi[0][k1];
                // col 64 (kq_f = -64): W1 = (64*sc, kp*sc);
                // W2 = ((4096 - kp^2)*sc, 128*kp*sc)
                float w1r = 64.0f * scale;
                gr[1][k1] = fvr[1][k1] * w1r - fvi[1][k1] * kps;
                gi[1][k1] = fvr[1][k1] * kps + fvi[1][k1] * w1r;
                float A4 = (4096.0f - kp * kp) * scale;
                float B4 = 128.0f * kps;
                gr[3][k1] = A4 * fvr[1][k1] - B4 * fvi[1][k1];
                gi[3][k1] = A4 * fvi[1][k1] + B4 * fvr[1][k1];
            }
            // slots: [0]=Y1 col0, [1]=Y1 col64, [2]=Y2 col0, [3]=Y2 col64
        }

        fft_inv_n<4>(gr, gi, T, t);

        float msgn = mirror_conj ? -1.0f : 1.0f;
        float4* y;
        y = (float4*)(g_Y1 + ((size_t)s * NSIDE + qsP) * NSIDE + 4 * t);
        y[0] = make_float4(gr[0][0], gi[0][0], gr[0][1], gi[0][1]);
        y[1] = make_float4(gr[0][2], gi[0][2], gr[0][3], gi[0][3]);
        y = (float4*)(g_Y1 + ((size_t)s * NSIDE + qsM) * NSIDE + 4 * t);
        y[0] = make_float4(gr[1][0], msgn * gi[1][0], gr[1][1], msgn * gi[1][1]);
        y[1] = make_float4(gr[1][2], msgn * gi[1][2], gr[1][3], msgn * gi[1][3]);
        y = (float4*)(g_Y2 + ((size_t)s * NSIDE + qsP) * NSIDE + 4 * t);
        y[0] = make_float4(gr[2][0], gi[2][0], gr[2][1], gi[2][1]);
        y[1] = make_float4(gr[2][2], gi[2][2], gr[2][3], gi[2][3]);
        y = (float4*)(g_Y2 + ((size_t)s * NSIDE + qsM) * NSIDE + 4 * t);
        y[0] = make_float4(gr[3][0], msgn * gi[3][0], gr[3][1], msgn * gi[3][1]);
        y[1] = make_float4(gr[3][2], msgn * gi[3][2], gr[3][3], msgn * gi[3][3]);
    }
}

// ---------------------------------------------------------------------------
// P2: per (slice, 32-row tile). float4 tile loads, stride-33 smem transpose,
// inverse FFT over q (register/shuffle), fused fast epilogue.  (unchanged)
// ---------------------------------------------------------------------------
__global__ void __launch_bounds__(512, 2) p2_kernel(float* __restrict__ out,
                                                    const float* __restrict__ df,
                                                    const float* __restrict__ d2f)
{
    extern __shared__ float sm[];
    float* T1r = sm;
    float* T1i = T1r + 4224;
    float* T2r = T1i + 4224;
    float* T2i = T2r + 4224;

    const int s    = blockIdx.x;
    const int m0   = blockIdx.y * 32;
    const int tid  = threadIdx.x;
    const int u    = tid >> 5;
    const int t    = tid & 31;

    Tw T;
    make_tw(T, t);

    const float4* y1v = (const float4*)(g_Y1 + (size_t)s * (NSIDE * NSIDE));
    const float4* y2v = (const float4*)(g_Y2 + (size_t)s * (NSIDE * NSIDE));
    const int mb = blockIdx.y * 16;

#pragma unroll
    for (int i = 0; i < 4; ++i) {
        int e  = i * 512 + tid;
        int q  = e >> 4;
        int mp = e & 15;
        float4 v1 = y1v[q * 64 + mb + mp];
        T1r[q * 33 + 2 * mp]     = v1.x;
        T1i[q * 33 + 2 * mp]     = v1.y;
        T1r[q * 33 + 2 * mp + 1] = v1.z;
        T1i[q * 33 + 2 * mp + 1] = v1.w;
        float4 v2 = y2v[q * 64 + mb + mp];
        T2r[q * 33 + 2 * mp]     = v2.x;
        T2i[q * 33 + 2 * mp]     = v2.y;
        T2r[q * 33 + 2 * mp + 1] = v2.z;
        T2i[q * 33 + 2 * mp + 1] = v2.w;
    }
    __syncthreads();

    const int c = s & 63;
    float df0 = df[2 * c], df1 = df[2 * c + 1];
    float ed  = expf(df0);
    float dfcr = ed * cosf(df1), dfci = ed * sinf(df1);
    float d20 = d2f[2 * c], d21 = d2f[2 * c + 1];
    float inv_nf = 0.5f / (dfcr * dfcr + dfci * dfci);
    float hrr = (d20 * dfcr + d21 * dfci) * inv_nf;
    float hri = (d21 * dfcr - d20 * dfci) * inv_nf;

    const float EPS2   = 1e-6f;
    const float LN_EPS = -6.9077552790f;
    const float TR_MIN = -2.5902671570f;

#pragma unroll 1
    for (int iter = 0; iter < 2; ++iter) {
        int mm = iter * 16 + u;
        int m  = m0 + mm;

        float dxr[1][4], dxi[1][4];
#pragma unroll
        for (int k1 = 0; k1 < 4; ++k1) {
            int qs = t + (k1 << 5);
            dxr[0][k1] = T1r[qs * 33 + mm];
            dxi[0][k1] = T1i[qs * 33 + mm];
        }
        fft_inv_n<1>(dxr, dxi, T, t);

        float d2r_[1][4], d2i_[1][4];
#pragma unroll
        for (int k1 = 0; k1 < 4; ++k1) {
            int qs = t + (k1 << 5);
            d2r_[0][k1] = T2r[qs * 33 + mm];
            d2i_[0][k1] = T2i[qs * 33 + mm];
        }
        fft_inv_n<1>(d2r_, d2i_, T, t);

        float oh[4], oa[4], op[4], ot[4], os[4];
#pragma unroll
        for (int j = 0; j < 4; ++j) {
            float Dr0 = dxr[0][j], Di0 = dxi[0][j];
            float d2r = d2r_[0][j], d2i = d2i_[0][j];

            float h = Dr0 * Dr0 + Di0 * Di0;
            bool valid = (h >= EPS2);
            float Dr = valid ? Dr0 : 1.0f;
            float Di = valid ? Di0 : 0.0f;
            float nD = valid ? h : 1.0f;

            float lnA = 0.0f, Phi = 0.0f;
            if (valid) {
                float la = df0 - 0.5f * __logf(h);
                lnA = fminf(3.0f, fmaxf(-3.0f, la));
                float a2r = dfcr * Dr + dfci * Di;
                float a2i = dfci * Dr - dfcr * Di;
                Phi = fatan2f(a2i, a2r);
            }

            float t1r = d2r * dfcr - d2i * dfci;
            float t1i = d2r * dfci + d2i * dfcr;
            float D2r = Dr * Dr - Di * Di;
            float D2i = 2.0f * Dr * Di;
            float inv2h = 0.5f * __fdividef(1.0f, nD * nD);
            float anr = (t1r * D2r + t1i * D2i) * inv2h - hrr;
            float ani = (t1i * D2r - t1r * D2i) * inv2h - hri;

            float na = anr * anr + ani * ani;
            bool tm = valid && (na >= EPS2);
            float lnT = LN_EPS, Psi = 0.0f;
            if (tm) {
                float lt = 0.5f * __logf(na);
                lnT = fminf(3.0f, fmaxf(TR_MIN, lt));
                Psi = fatan2f(ani, anr);
            }

            oh[j] = h; oa[j] = lnA; op[j] = Phi; ot[j] = lnT; os[j] = Psi;
        }

        size_t base = (size_t)s * 16384 + (size_t)m * 128;
        ((float4*)(out + base))[t]             = *(float4*)oh;
        ((float4*)(out + PLANE + base))[t]     = *(float4*)oa;
        ((float4*)(out + 2 * PLANE + base))[t] = *(float4*)op;
        ((float4*)(out + 3 * PLANE + base))[t] = *(float4*)ot;
        ((float4*)(out + 4 * PLANE + base))[t] = *(float4*)os;
    }
}

extern "C" void kernel_launch(void* const* d_in, const int* in_sizes, int n_in,
                              void* d_out, int out_size)
{
    const float* x   = (const float*)d_in[0];
    const float* df  = (const float*)d_in[1];
    const float* d2f = (const float*)d_in[2];
    float* out = (float*)d_out;

    const int P1_SMEM = 2 * 128 * 128 * 4;   // 131072 B
    const int P2_SMEM = 4 * 4224 * 4;        // 67584 B

    cudaFuncSetAttribute(p1_kernel, cudaFuncAttributeMaxDynamicSharedMemorySize, P1_SMEM);
    cudaFuncSetAttribute(p2_kernel, cudaFuncAttributeMaxDynamicSharedMemorySize, P2_SMEM);

    p1_kernel<<<SLICES, 512, P1_SMEM>>>(x);
    p2_kernel<<<dim3(SLICES, 4), 512, P2_SMEM>>>(out, df, d2f);
}

// round 8
// speedup vs baseline: 1.8338x; 1.1092x over previous
#include <cuda_runtime.h>
#include <math.h>

#define NSIDE 128
#define SLICES 1024
#define PLANE 16777216ull   // 1024 * 128 * 128

// Scratch: Y1/Y2 stored [slice][qs][n-natural] as float2, qs = storage-permuted q
__device__ float2 g_Y1[SLICES * NSIDE * NSIDE];
__device__ float2 g_Y2[SLICES * NSIDE * NSIDE];

// ---------------------------------------------------------------------------
// Register/shuffle 128-pt FFT, batched NF-ways for ILP: 128 = 32 lanes x 4 regs.
// Input layout (P4):  thread t holds x[4t + j], j = reg 0..3
// Output layout (SP): thread b, reg k1 holds X[bitrev5(b) + 32*k1]
// Inverse consumes SP, produces P4, UNSCALED (x128); scaling folded by caller.
// ---------------------------------------------------------------------------
struct Tw {
    float w16r, w16i, w8r, w8i, w4r, w4i, w2r, w2i;
    float c1, s1, c2, s2, c3, s3;
};

__device__ __forceinline__ void stage_tw(int t, int h, float& cr, float& ci)
{
    if (t & h) {
        sincospif(-(float)(t & (h - 1)) / (float)h, &ci, &cr);
    } else { cr = 1.0f; ci = 0.0f; }
}

__device__ __forceinline__ void make_tw(Tw& T, int t)
{
    int br = __brev(t) >> 27;
    sincospif((float)br * (1.0f / 64.0f), &T.s1, &T.c1);
    sincospif((float)br * (1.0f / 32.0f), &T.s2, &T.c2);
    sincospif((float)(3 * br) * (1.0f / 64.0f), &T.s3, &T.c3);
    stage_tw(t, 16, T.w16r, T.w16i);
    stage_tw(t, 8,  T.w8r,  T.w8i);
    stage_tw(t, 4,  T.w4r,  T.w4i);
    stage_tw(t, 2,  T.w2r,  T.w2i);
}

__device__ __forceinline__ void cmulm(float& ar, float& ai, float br, float bi)
{
    float r = ar * br - ai * bi;
    ai = ar * bi + ai * br;
    ar = r;
}

template <int NF, int H>
__device__ __forceinline__ void lstage_f(float (&vr)[NF][4], float (&vi)[NF][4],
                                         float twr, float twi, int t)
{
    float e = (t & H) ? -1.0f : 1.0f;
    float pr[NF][4], pi[NF][4];
#pragma unroll
    for (int f = 0; f < NF; ++f)
#pragma unroll
        for (int r = 0; r < 4; ++r) {
            pr[f][r] = __shfl_xor_sync(0xffffffffu, vr[f][r], H);
            pi[f][r] = __shfl_xor_sync(0xffffffffu, vi[f][r], H);
        }
#pragma unroll
    for (int f = 0; f < NF; ++f)
#pragma unroll
        for (int r = 0; r < 4; ++r) {
            float ur = fmaf(e, vr[f][r], pr[f][r]);
            float ui = fmaf(e, vi[f][r], pi[f][r]);
            vr[f][r] = ur * twr - ui * twi;
            vi[f][r] = fmaf(ur, twi, ui * twr);
        }
}

template <int NF>
__device__ __forceinline__ void lstage_f1(float (&vr)[NF][4], float (&vi)[NF][4], int t)
{
    float e = (t & 1) ? -1.0f : 1.0f;
    float pr[NF][4], pi[NF][4];
#pragma unroll
    for (int f = 0; f < NF; ++f)
#pragma unroll
        for (int r = 0; r < 4; ++r) {
            pr[f][r] = __shfl_xor_sync(0xffffffffu, vr[f][r], 1);
            pi[f][r] = __shfl_xor_sync(0xffffffffu, vi[f][r], 1);
        }
#pragma unroll
    for (int f = 0; f < NF; ++f)
#pragma unroll
        for (int r = 0; r < 4; ++r) {
            vr[f][r] = fmaf(e, vr[f][r], pr[f][r]);
            vi[f][r] = fmaf(e, vi[f][r], pi[f][r]);
        }
}

template <int NF, int H>
__device__ __forceinline__ void lstage_i(float (&vr)[NF][4], float (&vi)[NF][4],
                                         float twr, float twi, int t)
{
    float e = (t & H) ? -1.0f : 1.0f;
    float ar[NF][4], ai[NF][4], pr[NF][4], pi[NF][4];
#pragma unroll
    for (int f = 0; f < NF; ++f)
#pragma unroll
        for (int r = 0; r < 4; ++r) {
            ar[f][r] = fmaf(vi[f][r], twi, vr[f][r] * twr);
            ai[f][r] = vi[f][r] * twr - vr[f][r] * twi;
        }
#pragma unroll
    for (int f = 0; f < NF; ++f)
#pragma unroll
        for (int r = 0; r < 4; ++r) {
            pr[f][r] = __shfl_xor_sync(0xffffffffu, ar[f][r], H);
            pi[f][r] = __shfl_xor_sync(0xffffffffu, ai[f][r], H);
        }
#pragma unroll
    for (int f = 0; f < NF; ++f)
#pragma unroll
        for (int r = 0; r < 4; ++r) {
            vr[f][r] = fmaf(e, ar[f][r], pr[f][r]);
            vi[f][r] = fmaf(e, ai[f][r], pi[f][r]);
        }
}

template <int NF>
__device__ __forceinline__ void lstage_i1(float (&vr)[NF][4], float (&vi)[NF][4], int t)
{
    float e = (t & 1) ? -1.0f : 1.0f;
    float pr[NF][4], pi[NF][4];
#pragma unroll
    for (int f = 0; f < NF; ++f)
#pragma unroll
        for (int r = 0; r < 4; ++r) {
            pr[f][r] = __shfl_xor_sync(0xffffffffu, vr[f][r], 1);
            pi[f][r] = __shfl_xor_sync(0xffffffffu, vi[f][r], 1);
        }
#pragma unroll
    for (int f = 0; f < NF; ++f)
#pragma unroll
        for (int r = 0; r < 4; ++r) {
            vr[f][r] = fmaf(e, vr[f][r], pr[f][r]);
            vi[f][r] = fmaf(e, vi[f][r], pi[f][r]);
        }
}

template <int NF>
__device__ __forceinline__ void fft_fwd_n(float (&vr)[NF][4], float (&vi)[NF][4],
                                          const Tw& T, int t)
{
    lstage_f<NF, 16>(vr, vi, T.w16r, T.w16i, t);
    lstage_f<NF, 8>(vr, vi, T.w8r, T.w8i, t);
    lstage_f<NF, 4>(vr, vi, T.w4r, T.w4i, t);
    lstage_f<NF, 2>(vr, vi, T.w2r, T.w2i, t);
    lstage_f1<NF>(vr, vi, t);
#pragma unroll
    for (int f = 0; f < NF; ++f) {
        cmulm(vr[f][1], vi[f][1], T.c1, -T.s1);
        cmulm(vr[f][2], vi[f][2], T.c2, -T.s2);
        cmulm(vr[f][3], vi[f][3], T.c3, -T.s3);
        float s02r = vr[f][0] + vr[f][2], s02i = vi[f][0] + vi[f][2];
        float d02r = vr[f][0] - vr[f][2], d02i = vi[f][0] - vi[f][2];
        float s13r = vr[f][1] + vr[f][3], s13i = vi[f][1] + vi[f][3];
        float d13r = vr[f][1] - vr[f][3], d13i = vi[f][1] - vi[f][3];
        vr[f][0] = s02r + s13r; vi[f][0] = s02i + s13i;
        vr[f][2] = s02r - s13r; vi[f][2] = s02i - s13i;
        vr[f][1] = d02r + d13i; vi[f][1] = d02i - d13r;
        vr[f][3] = d02r - d13i; vi[f][3] = d02i + d13r;
    }
}

template <int NF>
__device__ __forceinline__ void fft_inv_n(float (&vr)[NF][4], float (&vi)[NF][4],
                                          const Tw& T, int t)
{
#pragma unroll
    for (int f = 0; f < NF; ++f) {
        float s02r = vr[f][0] + vr[f][2], s02i = vi[f][0] + vi[f][2];
        float d02r = vr[f][0] - vr[f][2], d02i = vi[f][0] - vi[f][2];
        float s13r = vr[f][1] + vr[f][3], s13i = vi[f][1] + vi[f][3];
        float d13r = vr[f][1] - vr[f][3], d13i = vi[f][1] - vi[f][3];
        vr[f][0] = s02r + s13r; vi[f][0] = s02i + s13i;
        vr[f][2] = s02r - s13r; vi[f][2] = s02i - s13i;
        vr[f][1] = d02r - d13i; vi[f][1] = d02i + d13r;
        vr[f][3] = d02r + d13i; vi[f][3] = d02i - d13r;
        cmulm(vr[f][1], vi[f][1], T.c1, T.s1);
        cmulm(vr[f][2], vi[f][2], T.c2, T.s2);
        cmulm(vr[f][3], vi[f][3], T.c3, T.s3);
    }
    lstage_i1<NF>(vr, vi, t);
    lstage_i<NF, 2>(vr, vi, T.w2r, T.w2i, t);
    lstage_i<NF, 4>(vr, vi, T.w4r, T.w4i, t);
    lstage_i<NF, 8>(vr, vi, T.w8r, T.w8i, t);
    lstage_i<NF, 16>(vr, vi, T.w16r, T.w16i, t);
}

// Fast atan2: minimax odd poly, abs err ~1e-5 rad; sign/branch-cut identical
// to atan2f (copysign from y).
__device__ __forceinline__ float fatan2f(float y, float x)
{
    float ax = fabsf(x), ay = fabsf(y);
    float mx = fmaxf(ax, ay), mn = fminf(ax, ay);
    float a = __fdividef(mn, mx);
    float s = a * a;
    float p = -0.0117212f;
    p = fmaf(p, s, 0.05265332f);
    p = fmaf(p, s, -0.11643287f);
    p = fmaf(p, s, 0.19354346f);
    p = fmaf(p, s, -0.33262347f);
    p = fmaf(p, s, 0.99997726f);
    float r = p * a;
    if (ay > ax) r = 1.57079632679f - r;
    if (x < 0.0f) r = 3.14159265359f - r;
    return copysignf(r, y);
}

// storage column of spectral index kq (0..127): brev5 within 32-groups
__device__ __forceinline__ int st_of_kq(int kq)
{
    return (int)(__brev((unsigned)(kq & 31)) >> 27) + (kq & 96);
}

// ---------------------------------------------------------------------------
// P1: 256 threads (8 warps), 3 CTAs/SM. Half-spectrum smem (cols 0..63 in a
// 128x64 swizzled array + Nyquist col 64 in separate 128-entry arrays).
// Row phase: 64 packed real-pair FFTs, Hermitian split, store kq<=64.
// Column phase: 63 mirror units + special {0,64}; 1 fwd + 2x NF=2 inverse.
// ---------------------------------------------------------------------------
__global__ void __launch_bounds__(256, 3) p1_kernel(const float* __restrict__ x)
{
    extern __shared__ float sm[];
    float* Fre = sm;            // 128*64, row m stride 64, col swizzle ^C (C<32)
    float* Fim = sm + 8192;
    float* Nyr = sm + 16384;    // 128 (spectral col 64, per row m)
    float* Nyi = sm + 16512;

    const int s   = blockIdx.x;
    const int tid = threadIdx.x;
    const int u   = tid >> 5;   // 0..7
    const int t   = tid & 31;

    Tw T;
    make_tw(T, t);
    const int r5 = __brev(t) >> 27;
    const int tP = (t == 0) ? 0 : (int)(__brev((unsigned)(32 - r5)) >> 27);

    const float4* xs = (const float4*)(x + (size_t)s * (NSIDE * NSIDE));

    // ---- row phase: 4 iterations x 2 packed pairs (NF=2) ----
#pragma unroll 1
    for (int it = 0; it < 4; ++it) {
        int pr0 = it * 16 + u;
        int pr1 = pr0 + 8;
        float vr[2][4], vi[2][4];
        {
            float4 a = xs[(2 * pr0) * 32 + t];
            float4 b = xs[(2 * pr0 + 1) * 32 + t];
            vr[0][0] = a.x; vr[0][1] = a.y; vr[0][2] = a.z; vr[0][3] = a.w;
            vi[0][0] = b.x; vi[0][1] = b.y; vi[0][2] = b.z; vi[0][3] = b.w;
            float4 c = xs[(2 * pr1) * 32 + t];
            float4 d = xs[(2 * pr1 + 1) * 32 + t];
            vr[1][0] = c.x; vr[1][1] = c.y; vr[1][2] = c.z; vr[1][3] = c.w;
            vi[1][0] = d.x; vi[1][1] = d.y; vi[1][2] = d.z; vi[1][3] = d.w;
        }
        fft_fwd_n<2>(vr, vi, T, t);

#pragma unroll
        for (int f = 0; f < 2; ++f) {
            int m1 = 2 * (f == 0 ? pr0 : pr1);
            int m2 = m1 + 1;
            int C  = (m1 >> 2) & 31;     // m1 even -> same key for m2
            float Znr[4], Zni[4];
#pragma unroll
            for (int k1 = 0; k1 < 4; ++k1) {
                Znr[k1] = __shfl_sync(0xffffffffu, vr[f][3 - k1], tP);
                Zni[k1] = __shfl_sync(0xffffffffu, vi[f][3 - k1], tP);
            }
            if (t == 0) {
                Znr[0] = vr[f][0]; Zni[0] = vi[f][0];
                Znr[1] = vr[f][3]; Zni[1] = vi[f][3];
                Znr[2] = vr[f][2]; Zni[2] = vi[f][2];
                Znr[3] = vr[f][1]; Zni[3] = vi[f][1];
            }
#pragma unroll
            for (int k1 = 0; k1 < 2; ++k1) {
                float Far = 0.5f * (vr[f][k1] + Znr[k1]);
                float Fai = 0.5f * (vi[f][k1] - Zni[k1]);
                float Fbr = 0.5f * (vi[f][k1] + Zni[k1]);
                float Fbi = 0.5f * (Znr[k1] - vr[f][k1]);
                int col = (t + (k1 << 5)) ^ C;    // stays in [32k1, 32k1+32)
                Fre[(m1 << 6) + col] = Far;
                Fim[(m1 << 6) + col] = Fai;
                Fre[(m2 << 6) + col] = Fbr;
                Fim[(m2 << 6) + col] = Fbi;
            }
            if (t == 0) {
                // spectral col 64 (k1==2 slot)
                Nyr[m1] = 0.5f * (vr[f][2] + Znr[2]);
                Nyi[m1] = 0.5f * (vi[f][2] - Zni[2]);
                Nyr[m2] = 0.5f * (vi[f][2] + Zni[2]);
                Nyi[m2] = 0.5f * (Znr[2] - vr[f][2]);
            }
        }
    }
    __syncthreads();

    const float scale = 1.0f / 16384.0f;

    // ---- column phase: 8 iterations, 1 unit per warp ----
#pragma unroll 1
    for (int it = 0; it < 8; ++it) {
        int u_id = it * 8 + u;

        if (u_id < 63) {
            int kq = u_id + 1;             // 1..63
            int qsP = st_of_kq(kq);        // 0..63
            int qsM = st_of_kq(128 - kq);

            float fvr[1][4], fvi[1][4];
#pragma unroll
            for (int j = 0; j < 4; ++j) {
                int p = 4 * t + j;
                int sc = qsP ^ t;
                fvr[0][j] = Fre[(p << 6) + sc];
                fvi[0][j] = Fim[(p << 6) + sc];
            }
            fft_fwd_n<1>(fvr, fvi, T, t);

            float kqs = (float)kq * scale;

            // --- G1 pair ---
            float gr[2][4], gi[2][4];
#pragma unroll
            for (int k1 = 0; k1 < 4; ++k1) {
                int p_idx = r5 + (k1 << 5);
                float kp  = (p_idx < 64) ? (float)p_idx : (float)(p_idx - 128);
                float sgnM = (p_idx == 64) ? -1.0f : 1.0f;
                float kps = kp * scale;
                float Fr = fvr[0][k1], Fi = fvi[0][k1];
                float a = kqs * Fr, b = kps * Fi, c = kps * Fr, d = kqs * Fi;
                gr[0][k1] = -a - b;        gi[0][k1] = c - d;
                gr[1][k1] =  a - sgnM * b; gi[1][k1] = sgnM * c + d;
            }
            fft_inv_n<2>(gr, gi, T, t);
            {
                float4* y;
                y = (float4*)(g_Y1 + ((size_t)s * NSIDE + qsP) * NSIDE + 4 * t);
                y[0] = make_float4(gr[0][0], gi[0][0], gr[0][1], gi[0][1]);
                y[1] = make_float4(gr[0][2], gi[0][2], gr[0][3], gi[0][3]);
                y = (float4*)(g_Y1 + ((size_t)s * NSIDE + qsM) * NSIDE + 4 * t);
                y[0] = make_float4(gr[1][0], -gi[1][0], gr[1][1], -gi[1][1]);
                y[1] = make_float4(gr[1][2], -gi[1][2], gr[1][3], -gi[1][3]);
            }

            // --- G2 pair ---
#pragma unroll
            for (int k1 = 0; k1 < 4; ++k1) {
                int p_idx = r5 + (k1 << 5);
                float kp  = (p_idx < 64) ? (float)p_idx : (float)(p_idx - 128);
                float sgnM = (p_idx == 64) ? -1.0f : 1.0f;
                float Fr = fvr[0][k1], Fi = fvi[0][k1];
                float A = ((float)kq * (float)kq - kp * kp) * scale;
                float B = 2.0f * kp * kqs;
                float Bm = sgnM * B;
                gr[0][k1] = fmaf(A, Fr,  B * Fi);
                gi[0][k1] = fmaf(A, Fi, -B * Fr);
                gr[1][k1] = fmaf(A, Fr, -Bm * Fi);
                gi[1][k1] = fmaf(A, Fi,  Bm * Fr);
            }
            fft_inv_n<2>(gr, gi, T, t);
            {
                float4* y;
                y = (float4*)(g_Y2 + ((size_t)s * NSIDE + qsP) * NSIDE + 4 * t);
                y[0] = make_float4(gr[0][0], gi[0][0], gr[0][1], gi[0][1]);
                y[1] = make_float4(gr[0][2], gi[0][2], gr[0][3], gi[0][3]);
                y = (float4*)(g_Y2 + ((size_t)s * NSIDE + qsM) * NSIDE + 4 * t);
                y[0] = make_float4(gr[1][0], -gi[1][0], gr[1][1], -gi[1][1]);
                y[1] = make_float4(gr[1][2], -gi[1][2], gr[1][3], -gi[1][3]);
            }
        } else if (u_id == 63) {
            // special unit: spectral columns 0 (storage 0) and 64
            float fvr[2][4], fvi[2][4];
#pragma unroll
            for (int j = 0; j < 4; ++j) {
                int p = 4 * t + j;
                fvr[0][j] = Fre[(p << 6) + t];   // col 0, swizzle 0^t = t
                fvi[0][j] = Fim[(p << 6) + t];
                fvr[1][j] = Nyr[p];
                fvi[1][j] = Nyi[p];
            }
            fft_fwd_n<2>(fvr, fvi, T, t);

            // --- Y1 pair: col0 + col64 ---
            float gr[2][4], gi[2][4];
#pragma unroll
            for (int k1 = 0; k1 < 4; ++k1) {
                int p_idx = r5 + (k1 << 5);
                float kp  = (p_idx < 64) ? (float)p_idx : (float)(p_idx - 128);
                float kps = kp * scale;
                gr[0][k1] = -fvi[0][k1] * kps;
                gi[0][k1] =  fvr[0][k1] * kps;
                float w1r = 64.0f * scale;
                gr[1][k1] = fvr[1][k1] * w1r - fvi[1][k1] * kps;
                gi[1][k1] = fvr[1][k1] * kps + fvi[1][k1] * w1r;
            }
            fft_inv_n<2>(gr, gi, T, t);
            {
                float4* y;
                y = (float4*)(g_Y1 + ((size_t)s * NSIDE + 0) * NSIDE + 4 * t);
                y[0] = make_float4(gr[0][0], gi[0][0], gr[0][1], gi[0][1]);
                y[1] = make_float4(gr[0][2], gi[0][2], gr[0][3], gi[0][3]);
                y = (float4*)(g_Y1 + ((size_t)s * NSIDE + 64) * NSIDE + 4 * t);
                y[0] = make_float4(gr[1][0], gi[1][0], gr[1][1], gi[1][1]);
                y[1] = make_float4(gr[1][2], gi[1][2], gr[1][3], gi[1][3]);
            }

            // --- Y2 pair: col0 + col64 ---
#pragma unroll
            for (int k1 = 0; k1 < 4; ++k1) {
                int p_idx = r5 + (k1 << 5);
                float kp  = (p_idx < 64) ? (float)p_idx : (float)(p_idx - 128);
                float kps = kp * scale;
                float A0 = -kp * kps;
                gr[0][k1] = A0 * fvr[0][k1];
                gi[0][k1] = A0 * fvi[0][k1];
                float A4 = (4096.0f - kp * kp) * scale;
                float B4 = 128.0f * kps;
                gr[1][k1] = A4 * fvr[1][k1] - B4 * fvi[1][k1];
                gi[1][k1] = A4 * fvi[1][k1] + B4 * fvr[1][k1];
            }
            fft_inv_n<2>(gr, gi, T, t);
            {
                float4* y;
                y = (float4*)(g_Y2 + ((size_t)s * NSIDE + 0) * NSIDE + 4 * t);
                y[0] = make_float4(gr[0][0], gi[0][0], gr[0][1], gi[0][1]);
                y[1] = make_float4(gr[0][2], gi[0][2], gr[0][3], gi[0][3]);
                y = (float4*)(g_Y2 + ((size_t)s * NSIDE + 64) * NSIDE + 4 * t);
                y[0] = make_float4(gr[1][0], gi[1][0], gr[1][1], gi[1][1]);
                y[1] = make_float4(gr[1][2], gi[1][2], gr[1][3], gi[1][3]);
            }
        }
    }
}

// ---------------------------------------------------------------------------
// P2: per (slice, 32-row tile). float4 tile loads, stride-33 smem transpose,
// batched NF=2 inverse FFT over q, fused fast epilogue.
// ---------------------------------------------------------------------------
__global__ void __launch_bounds__(512, 2) p2_kernel(float* __restrict__ out,
                                                    const float* __restrict__ df,
                                                    const float* __restrict__ d2f)
{
    extern __shared__ float sm[];
    float* T1r = sm;
    float* T1i = T1r + 4224;
    float* T2r = T1i + 4224;
    float* T2i = T2r + 4224;

    const int s    = blockIdx.x;
    const int m0   = blockIdx.y * 32;
    const int tid  = threadIdx.x;
    const int u    = tid >> 5;
    const int t    = tid & 31;

    Tw T;
    make_tw(T, t);

    const float4* y1v = (const float4*)(g_Y1 + (size_t)s * (NSIDE * NSIDE));
    const float4* y2v = (const float4*)(g_Y2 + (size_t)s * (NSIDE * NSIDE));
    const int mb = blockIdx.y * 16;

#pragma unroll
    for (int i = 0; i < 4; ++i) {
        int e  = i * 512 + tid;
        int q  = e >> 4;
        int mp = e & 15;
        float4 v1 = y1v[q * 64 + mb + mp];
        T1r[q * 33 + 2 * mp]     = v1.x;
        T1i[q * 33 + 2 * mp]     = v1.y;
        T1r[q * 33 + 2 * mp + 1] = v1.z;
        T1i[q * 33 + 2 * mp + 1] = v1.w;
        float4 v2 = y2v[q * 64 + mb + mp];
        T2r[q * 33 + 2 * mp]     = v2.x;
        T2i[q * 33 + 2 * mp]     = v2.y;
        T2r[q * 33 + 2 * mp + 1] = v2.z;
        T2i[q * 33 + 2 * mp + 1] = v2.w;
    }
    __syncthreads();

    const int c = s & 63;
    float df0 = df[2 * c], df1 = df[2 * c + 1];
    float ed  = expf(df0);
    float dfcr = ed * cosf(df1), dfci = ed * sinf(df1);
    float d20 = d2f[2 * c], d21 = d2f[2 * c + 1];
    float inv_nf = 0.5f / (dfcr * dfcr + dfci * dfci);
    float hrr = (d20 * dfcr + d21 * dfci) * inv_nf;
    float hri = (d21 * dfcr - d20 * dfci) * inv_nf;

    const float EPS2   = 1e-6f;
    const float LN_EPS = -6.9077552790f;
    const float TR_MIN = -2.5902671570f;

#pragma unroll 1
    for (int iter = 0; iter < 2; ++iter) {
        int mm = iter * 16 + u;
        int m  = m0 + mm;

        float vr[2][4], vi[2][4];
#pragma unroll
        for (int k1 = 0; k1 < 4; ++k1) {
            int qs = t + (k1 << 5);
            vr[0][k1] = T1r[qs * 33 + mm];
            vi[0][k1] = T1i[qs * 33 + mm];
            vr[1][k1] = T2r[qs * 33 + mm];
            vi[1][k1] = T2i[qs * 33 + mm];
        }
        fft_inv_n<2>(vr, vi, T, t);

        float oh[4], oa[4], op[4], ot[4], os[4];
#pragma unroll
        for (int j = 0; j < 4; ++j) {
            float Dr0 = vr[0][j], Di0 = vi[0][j];
            float d2r = vr[1][j], d2i = vi[1][j];

            float h = Dr0 * Dr0 + Di0 * Di0;
            bool valid = (h >= EPS2);
            float Dr = valid ? Dr0 : 1.0f;
            float Di = valid ? Di0 : 0.0f;
            float nD = valid ? h : 1.0f;

            float lnA = 0.0f, Phi = 0.0f;
            if (valid) {
                float la = df0 - 0.5f * __logf(h);
                lnA = fminf(3.0f, fmaxf(-3.0f, la));
                float a2r = dfcr * Dr + dfci * Di;
                float a2i = dfci * Dr - dfcr * Di;
                Phi = fatan2f(a2i, a2r);
            }

            float t1r = d2r * dfcr - d2i * dfci;
            float t1i = d2r * dfci + d2i * dfcr;
            float D2r = Dr * Dr - Di * Di;
            float D2i = 2.0f * Dr * Di;
            float inv2h = 0.5f * __fdividef(1.0f, nD * nD);
            float anr = (t1r * D2r + t1i * D2i) * inv2h - hrr;
            float ani = (t1i * D2r - t1r * D2i) * inv2h - hri;

            float na = anr * anr + ani * ani;
            bool tm = valid && (na >= EPS2);
            float lnT = LN_EPS, Psi = 0.0f;
            if (tm) {
                float lt = 0.5f * __logf(na);
                lnT = fminf(3.0f, fmaxf(TR_MIN, lt));
                Psi = fatan2f(ani, anr);
            }

            oh[j] = h; oa[j] = lnA; op[j] = Phi; ot[j] = lnT; os[j] = Psi;
        }

        size_t base = (size_t)s * 16384 + (size_t)m * 128;
        ((float4*)(out + base))[t]             = *(float4*)oh;
        ((float4*)(out + PLANE + base))[t]     = *(float4*)oa;
        ((float4*)(out + 2 * PLANE + base))[t] = *(float4*)op;
        ((float4*)(out + 3 * PLANE + base))[t] = *(float4*)ot;
        ((float4*)(out + 4 * PLANE + base))[t] = *(float4*)os;
    }
}

extern "C" void kernel_launch(void* const* d_in, const int* in_sizes, int n_in,
                              void* d_out, int out_size)
{
    const float* x   = (const float*)d_in[0];
    const float* df  = (const float*)d_in[1];
    const float* d2f = (const float*)d_in[2];
    float* out = (float*)d_out;

    const int P1_SMEM = (2 * 128 * 64 + 2 * 128) * 4;  // 66560 B
    const int P2_SMEM = 4 * 4224 * 4;                  // 67584 B

    cudaFuncSetAttribute(p1_kernel, cudaFuncAttributeMaxDynamicSharedMemorySize, P1_SMEM);
    cudaFuncSetAttribute(p2_kernel, cudaFuncAttributeMaxDynamicSharedMemorySize, P2_SMEM);

    p1_kernel<<<SLICES, 256, P1_SMEM>>>(x);
    p2_kernel<<<dim3(SLICES, 4), 512, P2_SMEM>>>(out, df, d2f);
}